// round 12
// baseline (speedup 1.0000x reference)
#include <cuda_runtime.h>
#include <cuda_bf16.h>
#include <cstdint>

#define BB   8
#define LLEN 4096
#define CEMB 192
#define DIN  384
#define XD   20
#define DTR  12
#define NC   128
#define LC   32
#define MROWS (BB*LLEN)

// ---------------- scratch ----------------
__device__ float g_xh  [MROWS*CEMB];
__device__ float g_xz  [MROWS*2*DIN];
__device__ float g_xa  [MROWS*DIN];
__device__ float g_xdbl[MROWS*DTR];
__device__ float g_bc  [MROWS*8];
__device__ float g_y   [MROWS*DIN];
__device__ float g_hpart[BB*DIN*NC*4];
__device__ float g_sumdt[BB*DIN*NC];
__device__ float g_Hinit[BB*DIN*NC*4];
__device__ float g_A[2*DIN*4];
__device__ int   g_slow[2];
__device__ float g_Uf[4*DIN];
__device__ __nv_bfloat16 g_ahi[MROWS*DIN], g_alo[MROWS*DIN];     // xh then y
__device__ __nv_bfloat16 g_bhi[MROWS*CEMB], g_blo[MROWS*CEMB];   // h2
__device__ __nv_bfloat16 g_whi[768*CEMB], g_wlo[768*CEMB];       // weights

__device__ __forceinline__ uint32_t smem_u32(const void* p) {
    uint32_t a;
    asm("{ .reg .u64 t; cvta.to.shared.u64 t, %1; cvt.u32.u64 %0, t; }" : "=r"(a) : "l"(p));
    return a;
}
__device__ __forceinline__ void cvt_hilo(float4 v, uint32_t& h0, uint32_t& h1,
                                         uint32_t& l0, uint32_t& l1) {
    asm("cvt.rn.bf16x2.f32 %0, %1, %2;" : "=r"(h0) : "f"(v.y), "f"(v.x));
    asm("cvt.rn.bf16x2.f32 %0, %1, %2;" : "=r"(h1) : "f"(v.w), "f"(v.z));
    float a0 = v.x - __uint_as_float(h0 << 16);
    float a1 = v.y - __uint_as_float(h0 & 0xffff0000u);
    float a2 = v.z - __uint_as_float(h1 << 16);
    float a3 = v.w - __uint_as_float(h1 & 0xffff0000u);
    asm("cvt.rn.bf16x2.f32 %0, %1, %2;" : "=r"(l0) : "f"(a1), "f"(a0));
    asm("cvt.rn.bf16x2.f32 %0, %1, %2;" : "=r"(l1) : "f"(a3), "f"(a2));
}
__device__ __forceinline__ void hilo_scalar(float v, __nv_bfloat16& h, __nv_bfloat16& l) {
    h = __float2bfloat16(v);
    l = __float2bfloat16(v - __bfloat162float(h));
}

#define LDSM_X4(r0, r1, r2, r3, addr) \
    asm volatile("ldmatrix.sync.aligned.m8n8.x4.shared.b16 {%0,%1,%2,%3}, [%4];" \
        : "=r"(r0), "=r"(r1), "=r"(r2), "=r"(r3) : "r"(addr))
#define LDSM_X2(r0, r1, addr) \
    asm volatile("ldmatrix.sync.aligned.m8n8.x2.shared.b16 {%0,%1}, [%2];" \
        : "=r"(r0), "=r"(r1) : "r"(addr))
#define MMA_BF16(c, a, b) \
    asm volatile("mma.sync.aligned.m16n8k16.row.col.f32.bf16.bf16.f32 " \
        "{%0,%1,%2,%3}, {%4,%5,%6,%7}, {%8,%9}, {%0,%1,%2,%3};" \
        : "+f"((c)[0]), "+f"((c)[1]), "+f"((c)[2]), "+f"((c)[3]) \
        : "r"((a)[0]), "r"((a)[1]), "r"((a)[2]), "r"((a)[3]), "r"((b)[0]), "r"((b)[1]))
#define CP_ASYNC16(smaddr, gptr) \
    asm volatile("cp.async.cg.shared.global [%0], [%1], 16;" :: "r"(smaddr), "l"(gptr))
#define CP_COMMIT() asm volatile("cp.async.commit_group;" ::: "memory")
#define CP_WAIT(n)  asm volatile("cp.async.wait_group %0;" :: "n"(n) : "memory")

// ======================= bf16 HMMA GEMM, cp.async double-buffered, BK=32 =======================
// stage layout (pitch 80B = 32 bf16 + 16B pad; (5r+q)%8 bank perm => conflict-free ldmatrix):
//   AH 0..10240, AL 10240, WH 20480, WL 25600; stage size 30720; two stages.
#define ST_AH 0
#define ST_AL 10240
#define ST_WH 20480
#define ST_WL 25600
#define ST_SZ 30720

__global__ void __launch_bounds__(256, 3)
gemm_mma(const __nv_bfloat16* __restrict__ Ahi, const __nv_bfloat16* __restrict__ Alo,
         const __nv_bfloat16* __restrict__ Whi, const __nv_bfloat16* __restrict__ Wlo,
         float* __restrict__ C, __nv_bfloat16* __restrict__ Chi, __nv_bfloat16* __restrict__ Clo,
         int M, int N, int K, int out_bf16)
{
    extern __shared__ __align__(16) char sm[];
    const int tid = threadIdx.x, wid = tid >> 5, lane = tid & 31;
    const int wm = wid & 3, wn = wid >> 2;
    const int bm = blockIdx.y * 128, bn = blockIdx.x * 64;
    const uint32_t sb = smem_u32(sm);

    float acc[2][4][4];
    #pragma unroll
    for (int i = 0; i < 2; i++)
        #pragma unroll
        for (int j = 0; j < 4; j++)
            #pragma unroll
            for (int q = 0; q < 4; q++) acc[i][j][q] = 0.f;

    const int nkt = K >> 5;

    // async load of one stage (A: 512 chunks hi+lo, W: 256 chunks hi+lo)
    auto issue = [&](int kt, int st) {
        uint32_t base = sb + st * ST_SZ;
        int k0 = kt * 32;
        #pragma unroll
        for (int i = 0; i < 2; i++) {
            int c = tid + i * 256;
            int r = c >> 2, q = c & 3;
            size_t go = (size_t)(bm + r) * K + k0 + q * 8;
            uint32_t dst = base + r * 80 + q * 16;
            CP_ASYNC16(dst + ST_AH, Ahi + go);
            CP_ASYNC16(dst + ST_AL, Alo + go);
        }
        {
            int r = tid >> 2, q = tid & 3;
            size_t go = (size_t)(bn + r) * K + k0 + q * 8;
            uint32_t dst = base + r * 80 + q * 16;
            CP_ASYNC16(dst + ST_WH, Whi + go);
            CP_ASYNC16(dst + ST_WL, Wlo + go);
        }
        CP_COMMIT();
    };

    issue(0, 0);

    for (int kt = 0; kt < nkt; kt++) {
        int st = kt & 1;
        if (kt + 1 < nkt) {
            issue(kt + 1, st ^ 1);
            CP_WAIT(1);
        } else {
            CP_WAIT(0);
        }
        __syncthreads();
        uint32_t base = sb + st * ST_SZ;

        #pragma unroll
        for (int ks = 0; ks < 2; ks++) {
            uint32_t ah[2][4], al[2][4], bh[4][2], bl[4][2];
            #pragma unroll
            for (int mt = 0; mt < 2; mt++) {
                int r = wm * 32 + mt * 16 + (lane & 15);
                int ch = ks * 2 + (lane >> 4);
                uint32_t off = base + (uint32_t)(r * 80 + ch * 16);
                LDSM_X4(ah[mt][0], ah[mt][1], ah[mt][2], ah[mt][3], off + ST_AH);
                LDSM_X4(al[mt][0], al[mt][1], al[mt][2], al[mt][3], off + ST_AL);
            }
            #pragma unroll
            for (int nt = 0; nt < 4; nt++) {
                int rn = wn * 32 + nt * 8 + (lane & 7);
                int ch = ks * 2 + ((lane >> 3) & 1);
                uint32_t off = base + (uint32_t)(rn * 80 + ch * 16);
                LDSM_X2(bh[nt][0], bh[nt][1], off + ST_WH);
                LDSM_X2(bl[nt][0], bl[nt][1], off + ST_WL);
            }
            #pragma unroll
            for (int mt = 0; mt < 2; mt++)
                #pragma unroll
                for (int nt = 0; nt < 4; nt++) {
                    MMA_BF16(acc[mt][nt], ah[mt], bh[nt]);
                    MMA_BF16(acc[mt][nt], ah[mt], bl[nt]);
                    MMA_BF16(acc[mt][nt], al[mt], bh[nt]);
                }
        }
        __syncthreads();
    }

    if (!out_bf16) {
        #pragma unroll
        for (int mt = 0; mt < 2; mt++) {
            int row = bm + wm * 32 + mt * 16 + (lane >> 2);
            #pragma unroll
            for (int nt = 0; nt < 4; nt++) {
                int col = bn + wn * 32 + nt * 8 + (lane & 3) * 2;
                *(float2*)(C + (size_t)row * N + col)       = make_float2(acc[mt][nt][0], acc[mt][nt][1]);
                *(float2*)(C + (size_t)(row + 8) * N + col) = make_float2(acc[mt][nt][2], acc[mt][nt][3]);
            }
        }
    } else {
        #pragma unroll
        for (int mt = 0; mt < 2; mt++) {
            int row = bm + wm * 32 + mt * 16 + (lane >> 2);
            #pragma unroll
            for (int nt = 0; nt < 4; nt++) {
                int col = bn + wn * 32 + nt * 8 + (lane & 3) * 2;
                #pragma unroll
                for (int hh = 0; hh < 2; hh++) {
                    float a0 = acc[mt][nt][hh*2+0], a1 = acc[mt][nt][hh*2+1];
                    size_t off = (size_t)(row + hh*8) * N + col;
                    uint32_t h, l;
                    asm("cvt.rn.bf16x2.f32 %0, %1, %2;" : "=r"(h) : "f"(a1), "f"(a0));
                    float h0f = __uint_as_float(h << 16);
                    float h1f = __uint_as_float(h & 0xffff0000u);
                    asm("cvt.rn.bf16x2.f32 %0, %1, %2;" : "=r"(l) : "f"(a1 - h1f), "f"(a0 - h0f));
                    *(uint32_t*)(Chi + off) = h;
                    *(uint32_t*)(Clo + off) = l;
                }
            }
        }
    }
}

// ---------------- weight convert ----------------
__global__ void wcvt_k(const float* __restrict__ src, int n4) {
    int idx = blockIdx.x * blockDim.x + threadIdx.x;
    if (idx >= n4) return;
    float4 v = ((const float4*)src)[idx];
    uint32_t h0, h1, l0, l1;
    cvt_hilo(v, h0, h1, l0, l1);
    ((uint2*)g_whi)[idx] = make_uint2(h0, h1);
    ((uint2*)g_wlo)[idx] = make_uint2(l0, l1);
}

// ---------------- transpose + bf16 hi/lo ----------------
__global__ void transpose_k(const float* __restrict__ x) {
    __shared__ float t[32][33];
    int b = blockIdx.z;
    int l0 = blockIdx.x * 32, c0 = blockIdx.y * 32;
    int tx = threadIdx.x, ty = threadIdx.y;
    #pragma unroll
    for (int j = ty; j < 32; j += 8)
        t[j][tx] = x[((b*CEMB) + (c0 + j)) * LLEN + l0 + tx];
    __syncthreads();
    #pragma unroll
    for (int j = ty; j < 32; j += 8) {
        float v = t[tx][j];
        size_t idx = ((size_t)(b*LLEN) + (l0 + j)) * CEMB + c0 + tx;
        g_xh[idx] = v;
        __nv_bfloat16 h, l;
        hilo_scalar(v, h, l);
        g_ahi[idx] = h; g_alo[idx] = l;
    }
}

// ---------------- A structure prep ----------------
__global__ void prepA_k(const float* __restrict__ A_log) {
    int mix = blockIdx.x;
    int d = threadIdx.x;
    if (d == 0) g_slow[mix] = 0;
    __syncthreads();
    const float* al = A_log + mix * DIN * 4;
    float a[4];
    #pragma unroll
    for (int s = 0; s < 4; s++) {
        a[s] = -expf(al[d*4 + s]);
        g_A[(mix*DIN + d)*4 + s] = a[s];
    }
    bool ok = true;
    #pragma unroll
    for (int s = 0; s < 4; s++) {
        float want = (float)(s + 1) * a[0];
        if (fabsf(a[s] - want) > 1e-5f * fabsf(a[s]) + 1e-7f) ok = false;
    }
    if (!ok) atomicExch(&g_slow[mix], 1);
}

// ---------------- Uf = U_w @ Wout2 ----------------
__global__ void uf_k(const float* __restrict__ U, const float* __restrict__ Wout2) {
    __shared__ float Ush[4*CEMB];
    int k = threadIdx.x;
    for (int i = k; i < 4*CEMB; i += DIN) Ush[i] = U[i];
    __syncthreads();
    float acc0 = 0.f, acc1 = 0.f, acc2 = 0.f, acc3 = 0.f;
    for (int c = 0; c < CEMB; c++) {
        float w = Wout2[(size_t)c * DIN + k];
        acc0 = fmaf(Ush[0*CEMB + c], w, acc0);
        acc1 = fmaf(Ush[1*CEMB + c], w, acc1);
        acc2 = fmaf(Ush[2*CEMB + c], w, acc2);
        acc3 = fmaf(Ush[3*CEMB + c], w, acc3);
    }
    g_Uf[0*DIN + k] = acc0;
    g_Uf[1*DIN + k] = acc1;
    g_Uf[2*DIN + k] = acc2;
    g_Uf[3*DIN + k] = acc3;
}

// ---------------- depthwise causal conv + silu, rolling window ----------------
__global__ void __launch_bounds__(256)
conv_k(const float* __restrict__ w, const float* __restrict__ bias) {
    int idx = blockIdx.x * blockDim.x + threadIdx.x;
    if (idx >= (MROWS/8) * (DIN/4)) return;
    int d4 = idx % (DIN/4);
    int m8 = idx / (DIN/4);
    int d  = d4 * 4;
    int bl = m8 * 8;
    int l  = bl % LLEN;

    float4 wv0 = *(const float4*)(w + (d+0)*4);
    float4 wv1 = *(const float4*)(w + (d+1)*4);
    float4 wv2 = *(const float4*)(w + (d+2)*4);
    float4 wv3 = *(const float4*)(w + (d+3)*4);
    float4 bv  = *(const float4*)(bias + d);

    const float* p = g_xz + (size_t)bl * (2*DIN) + d;
    float* po = g_xa + (size_t)bl * DIN + d;
    float4 x1 = make_float4(0,0,0,0), x2 = x1, x3 = x1;
    if (l) {
        x3 = *(const float4*)(p - 3*2*DIN);
        x2 = *(const float4*)(p - 2*2*DIN);
        x1 = *(const float4*)(p - 2*DIN);
    }
    #pragma unroll
    for (int j = 0; j < 8; j++) {
        float4 x0 = *(const float4*)(p + j*2*DIN);
        float4 acc = bv;
        acc.x = fmaf(wv0.x, x3.x, acc.x); acc.y = fmaf(wv1.x, x3.y, acc.y);
        acc.z = fmaf(wv2.x, x3.z, acc.z); acc.w = fmaf(wv3.x, x3.w, acc.w);
        acc.x = fmaf(wv0.y, x2.x, acc.x); acc.y = fmaf(wv1.y, x2.y, acc.y);
        acc.z = fmaf(wv2.y, x2.z, acc.z); acc.w = fmaf(wv3.y, x2.w, acc.w);
        acc.x = fmaf(wv0.z, x1.x, acc.x); acc.y = fmaf(wv1.z, x1.y, acc.y);
        acc.z = fmaf(wv2.z, x1.z, acc.z); acc.w = fmaf(wv3.z, x1.w, acc.w);
        acc.x = fmaf(wv0.w, x0.x, acc.x); acc.y = fmaf(wv1.w, x0.y, acc.y);
        acc.z = fmaf(wv2.w, x0.z, acc.z); acc.w = fmaf(wv3.w, x0.w, acc.w);
        float4 s;
        s.x = __fdividef(acc.x, 1.f + __expf(-acc.x));
        s.y = __fdividef(acc.y, 1.f + __expf(-acc.y));
        s.z = __fdividef(acc.z, 1.f + __expf(-acc.z));
        s.w = __fdividef(acc.w, 1.f + __expf(-acc.w));
        *(float4*)(po + j*DIN) = s;
        x3 = x2; x2 = x1; x1 = x0;
    }
}

// ---------------- x_proj ----------------
__global__ void __launch_bounds__(256)
xproj_k(const float* __restrict__ W) {
    __shared__ __align__(16) float Wsh[XD * DIN];
    for (int i = threadIdx.x; i < XD*DIN; i += 256) Wsh[i] = W[i];
    __syncthreads();
    int warp = threadIdx.x >> 5, lane = threadIdx.x & 31;
    int m0 = blockIdx.x * 32;
    for (int r = warp; r < 32; r += 8) {
        int m = m0 + r;
        const float4* ar = (const float4*)(g_xa + (size_t)m * DIN);
        float acc[XD];
        #pragma unroll
        for (int n = 0; n < XD; n++) acc[n] = 0.f;
        #pragma unroll
        for (int it = 0; it < 3; it++) {
            int k4 = lane + it * 32;
            float4 a = ar[k4];
            #pragma unroll
            for (int n = 0; n < XD; n++) {
                const float4 wv = *(const float4*)(Wsh + n*DIN + k4*4);
                acc[n] = fmaf(a.x, wv.x, fmaf(a.y, wv.y, fmaf(a.z, wv.z, fmaf(a.w, wv.w, acc[n]))));
            }
        }
        float myv = 0.f;
        #pragma unroll
        for (int n = 0; n < XD; n++) {
            float v = acc[n];
            #pragma unroll
            for (int off = 16; off > 0; off >>= 1)
                v += __shfl_xor_sync(0xffffffffu, v, off);
            if (lane == n) myv = v;
        }
        if (lane < DTR) g_xdbl[(size_t)m*DTR + lane] = myv;
        else if (lane < XD) g_bc[(size_t)m*8 + lane - DTR] = myv;
    }
}

// ---------------- scan pass 1 ----------------
__global__ void scan1_k(const float* __restrict__ dtw, const float* __restrict__ dtb, int mix) {
    __shared__ float Bsm[LC][4];
    __shared__ float Xd[LC][DTR];
    int chunk = blockIdx.x, b = blockIdx.y, d = threadIdx.x;
    int l0 = chunk * LC;
    if (threadIdx.x < LC*4) {
        int l = threadIdx.x >> 2, s = threadIdx.x & 3;
        Bsm[l][s] = g_bc[((size_t)(b*LLEN + l0 + l))*8 + s];
    }
    {
        int l = threadIdx.x / DTR, r = threadIdx.x - l*DTR;
        Xd[l][r] = g_xdbl[((size_t)(b*LLEN + l0 + l))*DTR + r];
    }
    __syncthreads();
    int slow = g_slow[mix];
    const float* Ab = g_A + (mix*DIN + d)*4;
    float Av0 = Ab[0], Av1 = Ab[1], Av2 = Ab[2], Av3 = Ab[3];
    const float4* w4 = (const float4*)(dtw + d * DTR);
    float4 dw0 = w4[0], dw1 = w4[1], dw2 = w4[2];
    float pb = dtb[d];
    float h0 = 0.f, h1 = 0.f, h2 = 0.f, h3 = 0.f, sd = 0.f;
    const float* pa = g_xa + (size_t)(b*LLEN + l0)*DIN + d;
    #pragma unroll 4
    for (int l = 0; l < LC; l++) {
        float xav = pa[l*DIN];
        const float* xr = Xd[l];
        float p = pb;
        p = fmaf(xr[0], dw0.x, p);  p = fmaf(xr[1], dw0.y, p);
        p = fmaf(xr[2], dw0.z, p);  p = fmaf(xr[3], dw0.w, p);
        p = fmaf(xr[4], dw1.x, p);  p = fmaf(xr[5], dw1.y, p);
        p = fmaf(xr[6], dw1.z, p);  p = fmaf(xr[7], dw1.w, p);
        p = fmaf(xr[8], dw2.x, p);  p = fmaf(xr[9], dw2.y, p);
        p = fmaf(xr[10], dw2.z, p); p = fmaf(xr[11], dw2.w, p);
        float dtv = (p > 20.f) ? p : __logf(1.f + __expf(p));
        float dbu = dtv * xav;
        sd += dtv;
        float b0 = Bsm[l][0], b1 = Bsm[l][1], b2 = Bsm[l][2], b3 = Bsm[l][3];
        if (!slow) {
            float e = __expf(Av0 * dtv);
            float q = e;
            h0 = fmaf(q, h0, dbu*b0); q *= e;
            h1 = fmaf(q, h1, dbu*b1); q *= e;
            h2 = fmaf(q, h2, dbu*b2); q *= e;
            h3 = fmaf(q, h3, dbu*b3);
        } else {
            h0 = fmaf(__expf(dtv*Av0), h0, dbu*b0);
            h1 = fmaf(__expf(dtv*Av1), h1, dbu*b1);
            h2 = fmaf(__expf(dtv*Av2), h2, dbu*b2);
            h3 = fmaf(__expf(dtv*Av3), h3, dbu*b3);
        }
    }
    int o = ((b*DIN) + d)*NC + chunk;
    ((float4*)g_hpart)[o] = make_float4(h0, h1, h2, h3);
    g_sumdt[o] = sd;
}

// ---------------- scan pass 2 ----------------
__global__ void scan2_k(int mix) {
    int t = blockIdx.x * blockDim.x + threadIdx.x;
    if (t >= BB*DIN) return;
    int d = t % DIN;
    const float* Ab = g_A + (mix*DIN + d)*4;
    float Av0 = Ab[0], Av1 = Ab[1], Av2 = Ab[2], Av3 = Ab[3];
    float H0 = 0.f, H1 = 0.f, H2 = 0.f, H3 = 0.f;
    for (int c = 0; c < NC; c++) {
        int o = t*NC + c;
        ((float4*)g_Hinit)[o] = make_float4(H0, H1, H2, H3);
        float4 hp = ((const float4*)g_hpart)[o];
        float sd = g_sumdt[o];
        H0 = fmaf(__expf(Av0*sd), H0, hp.x);
        H1 = fmaf(__expf(Av1*sd), H1, hp.y);
        H2 = fmaf(__expf(Av2*sd), H2, hp.z);
        H3 = fmaf(__expf(Av3*sd), H3, hp.w);
    }
}

// ---------------- scan pass 3 ----------------
__global__ void scan3_k(const float* __restrict__ dtw, const float* __restrict__ dtb,
                        const float* __restrict__ Dw, int mix, int write_bf16) {
    __shared__ float Bsm[LC][4];
    __shared__ float Csm[LC][4];
    __shared__ float Xd[LC][DTR];
    int chunk = blockIdx.x, b = blockIdx.y, d = threadIdx.x;
    int l0 = chunk * LC;
    if (threadIdx.x < LC*8) {
        int l = threadIdx.x >> 3, s = threadIdx.x & 7;
        float v = g_bc[((size_t)(b*LLEN + l0 + l))*8 + s];
        if (s < 4) Bsm[l][s] = v; else Csm[l][s-4] = v;
    }
    {
        int l = threadIdx.x / DTR, r = threadIdx.x - l*DTR;
        Xd[l][r] = g_xdbl[((size_t)(b*LLEN + l0 + l))*DTR + r];
    }
    __syncthreads();
    int slow = g_slow[mix];
    const float* Ab = g_A + (mix*DIN + d)*4;
    float Av0 = Ab[0], Av1 = Ab[1], Av2 = Ab[2], Av3 = Ab[3];
    const float4* w4 = (const float4*)(dtw + d * DTR);
    float4 dw0 = w4[0], dw1 = w4[1], dw2 = w4[2];
    float pb = dtb[d];
    float Dd = Dw[d];
    int o = ((b*DIN) + d)*NC + chunk;
    float4 Hi = ((const float4*)g_Hinit)[o];
    float h0 = Hi.x, h1 = Hi.y, h2 = Hi.z, h3 = Hi.w;
    size_t base = (size_t)(b*LLEN + l0)*DIN + d;
    const float* pa = g_xa + base;
    const float* pz = g_xz + (size_t)(b*LLEN + l0)*(2*DIN) + DIN + d;
    #pragma unroll 4
    for (int l = 0; l < LC; l++) {
        float xav = pa[l*DIN];
        const float* xr = Xd[l];
        float p = pb;
        p = fmaf(xr[0], dw0.x, p);  p = fmaf(xr[1], dw0.y, p);
        p = fmaf(xr[2], dw0.z, p);  p = fmaf(xr[3], dw0.w, p);
        p = fmaf(xr[4], dw1.x, p);  p = fmaf(xr[5], dw1.y, p);
        p = fmaf(xr[6], dw1.z, p);  p = fmaf(xr[7], dw1.w, p);
        p = fmaf(xr[8], dw2.x, p);  p = fmaf(xr[9], dw2.y, p);
        p = fmaf(xr[10], dw2.z, p); p = fmaf(xr[11], dw2.w, p);
        float dtv = (p > 20.f) ? p : __logf(1.f + __expf(p));
        float dbu = dtv * xav;
        float b0 = Bsm[l][0], b1 = Bsm[l][1], b2 = Bsm[l][2], b3 = Bsm[l][3];
        if (!slow) {
            float e = __expf(Av0 * dtv);
            float q = e;
            h0 = fmaf(q, h0, dbu*b0); q *= e;
            h1 = fmaf(q, h1, dbu*b1); q *= e;
            h2 = fmaf(q, h2, dbu*b2); q *= e;
            h3 = fmaf(q, h3, dbu*b3);
        } else {
            h0 = fmaf(__expf(dtv*Av0), h0, dbu*b0);
            h1 = fmaf(__expf(dtv*Av1), h1, dbu*b1);
            h2 = fmaf(__expf(dtv*Av2), h2, dbu*b2);
            h3 = fmaf(__expf(dtv*Av3), h3, dbu*b3);
        }
        float y = h0*Csm[l][0] + h1*Csm[l][1] + h2*Csm[l][2] + h3*Csm[l][3];
        y = fmaf(xav, Dd, y);
        float zv = pz[l*2*DIN];
        float zs = __fdividef(zv, 1.f + __expf(-zv));
        float yo = y * zs;
        if (write_bf16) {
            __nv_bfloat16 hb, lb;
            hilo_scalar(yo, hb, lb);
            g_ahi[base + l*DIN] = hb;
            g_alo[base + l*DIN] = lb;
        } else {
            g_y[base + l*DIN] = yo;
        }
    }
}

// ---------------- final ----------------
__global__ void final_k(const float* __restrict__ V,
                        const float* __restrict__ lng, const float* __restrict__ lnb,
                        float* __restrict__ out)
{
    __shared__ __align__(16) float Ufs[4*DIN];
    __shared__ float Vsh[CEMB*4];
    __shared__ float u[32][4];
    __shared__ float vs[32][193];
    __shared__ float mu[32], rsd[32];
    int b = blockIdx.y;
    int l0 = blockIdx.x * 32;
    int tid = threadIdx.x;
    for (int i = tid; i < 4*DIN; i += 256) Ufs[i] = g_Uf[i];
    for (int i = tid; i < 4*CEMB; i += 256) Vsh[i] = V[i];
    __syncthreads();
    if (tid < 128) {
        int p = tid >> 2, r = tid & 3;
        const float4* yr = (const float4*)(g_y + ((size_t)(b*LLEN) + l0 + p)*DIN);
        const float4* uf = (const float4*)(Ufs + r*DIN);
        float a = 0.f;
        #pragma unroll 8
        for (int c = 0; c < DIN/4; c++) {
            float4 yv = yr[c];
            float4 wv = uf[c];
            a = fmaf(yv.x, wv.x, fmaf(yv.y, wv.y, fmaf(yv.z, wv.z, fmaf(yv.w, wv.w, a))));
        }
        u[p][r] = a;
    }
    __syncthreads();
    for (int i = tid; i < 32*CEMB; i += 256) {
        int p = i / CEMB, c = i % CEMB;
        float v = g_xh[((size_t)(b*LLEN) + l0 + p)*CEMB + c];
        v = fmaf(Vsh[c*4+0], u[p][0], v);
        v = fmaf(Vsh[c*4+1], u[p][1], v);
        v = fmaf(Vsh[c*4+2], u[p][2], v);
        v = fmaf(Vsh[c*4+3], u[p][3], v);
        vs[p][c] = v;
    }
    __syncthreads();
    int warp = tid >> 5, lane = tid & 31;
    #pragma unroll
    for (int pp = 0; pp < 4; pp++) {
        int p = warp*4 + pp;
        float s = 0.f, ss = 0.f;
        for (int c = lane; c < CEMB; c += 32) {
            float v = vs[p][c];
            s += v; ss = fmaf(v, v, ss);
        }
        #pragma unroll
        for (int off = 16; off > 0; off >>= 1) {
            s  += __shfl_xor_sync(0xffffffffu, s, off);
            ss += __shfl_xor_sync(0xffffffffu, ss, off);
        }
        if (lane == 0) {
            float m = s * (1.f/CEMB);
            mu[p] = m;
            rsd[p] = rsqrtf(ss * (1.f/CEMB) - m*m + 1e-5f);
        }
    }
    __syncthreads();
    for (int c = warp; c < CEMB; c += 8) {
        int p = lane;
        float v = (vs[p][c] - mu[p]) * rsd[p] * lng[c] + lnb[c];
        out[((size_t)(b*CEMB) + c)*LLEN + l0 + lane] = v;
    }
}

// ---------------- launch ----------------
extern "C" void kernel_launch(void* const* d_in, const int* in_sizes, int n_in,
                              void* d_out, int out_size)
{
    const float* x         = (const float*)d_in[0];
    const float* in_proj_w = (const float*)d_in[1];
    const float* conv_w    = (const float*)d_in[2];
    const float* conv_b    = (const float*)d_in[3];
    const float* x_proj_w  = (const float*)d_in[4];
    const float* dt_proj_w = (const float*)d_in[5];
    const float* dt_proj_b = (const float*)d_in[6];
    const float* A_log     = (const float*)d_in[7];
    const float* Dw        = (const float*)d_in[8];
    const float* out_proj_w= (const float*)d_in[9];
    const float* U_w       = (const float*)d_in[10];
    const float* V_w       = (const float*)d_in[11];
    const float* ln_g      = (const float*)d_in[12];
    const float* ln_b      = (const float*)d_in[13];
    float* out = (float*)d_out;

    float* g_xz_p;  cudaGetSymbolAddress((void**)&g_xz_p,  g_xz);
    __nv_bfloat16 *ahi_p, *alo_p, *bhi_p, *blo_p, *whi_p, *wlo_p;
    cudaGetSymbolAddress((void**)&ahi_p, g_ahi);
    cudaGetSymbolAddress((void**)&alo_p, g_alo);
    cudaGetSymbolAddress((void**)&bhi_p, g_bhi);
    cudaGetSymbolAddress((void**)&blo_p, g_blo);
    cudaGetSymbolAddress((void**)&whi_p, g_whi);
    cudaGetSymbolAddress((void**)&wlo_p, g_wlo);

    const int GSMEM = 2 * ST_SZ;   // 61440
    cudaFuncSetAttribute(gemm_mma, cudaFuncAttributeMaxDynamicSharedMemorySize, GSMEM);

    transpose_k<<<dim3(LLEN/32, CEMB/32, BB), dim3(32, 8)>>>(x);
    prepA_k<<<2, DIN>>>(A_log);
    uf_k<<<1, DIN>>>(U_w, out_proj_w + (size_t)CEMB*DIN);

    for (int mix = 0; mix < 2; mix++) {
        const float* dtw = dt_proj_w + (size_t)mix*DIN*DTR;
        const float* dtb = dt_proj_b + mix*DIN;
        const __nv_bfloat16* Ain_hi = (mix == 0) ? ahi_p : bhi_p;
        const __nv_bfloat16* Ain_lo = (mix == 0) ? alo_p : blo_p;

        wcvt_k<<<(2*DIN*CEMB/4 + 255)/256, 256>>>(in_proj_w + (size_t)mix*2*DIN*CEMB, 2*DIN*CEMB/4);
        gemm_mma<<<dim3((2*DIN)/64, MROWS/128), 256, GSMEM>>>(
            Ain_hi, Ain_lo, whi_p, wlo_p, g_xz_p, nullptr, nullptr, MROWS, 2*DIN, CEMB, 0);
        conv_k<<<((MROWS/8)*(DIN/4) + 255)/256, 256>>>(conv_w + mix*DIN*4, conv_b + mix*DIN);
        xproj_k<<<MROWS/32, 256>>>(x_proj_w + (size_t)mix*XD*DIN);
        scan1_k<<<dim3(NC, BB), DIN>>>(dtw, dtb, mix);
        scan2_k<<<(BB*DIN + 255)/256, 256>>>(mix);
        scan3_k<<<dim3(NC, BB), DIN>>>(dtw, dtb, Dw + mix*DIN, mix, mix == 0 ? 1 : 0);
        if (mix == 0) {
            wcvt_k<<<(CEMB*DIN/4 + 255)/256, 256>>>(out_proj_w, CEMB*DIN/4);
            gemm_mma<<<dim3(CEMB/64, MROWS/128), 256, GSMEM>>>(
                ahi_p, alo_p, whi_p, wlo_p, nullptr, bhi_p, blo_p, MROWS, CEMB, DIN, 1);
        }
    }

    final_k<<<dim3(LLEN/32, BB), 256>>>(V_w, ln_g, ln_b, out);
}

// round 13
// speedup vs baseline: 1.1843x; 1.1843x over previous
#include <cuda_runtime.h>
#include <cuda_fp16.h>
#include <cstdint>

#define BB   8
#define LLEN 4096
#define CEMB 192
#define DIN  384
#define XD   20
#define DTR  12
#define NC   128
#define LC   32
#define MROWS (BB*LLEN)

// ---------------- scratch ----------------
__device__ float g_xh  [MROWS*CEMB];
__device__ float g_xz  [MROWS*2*DIN];
__device__ float g_xa  [MROWS*DIN];
__device__ float g_xdbl[MROWS*DTR];
__device__ float g_bc  [MROWS*8];
__device__ float g_y   [MROWS*DIN];
__device__ float g_hpart[BB*DIN*NC*4];
__device__ float g_sumdt[BB*DIN*NC];
__device__ float g_Hinit[BB*DIN*NC*4];
__device__ float g_A[2*DIN*4];
__device__ int   g_slow[2];
__device__ float g_Uf[4*DIN];
__device__ __half g_ah[MROWS*DIN];      // xh (cols 0..191 used) then y (384)
__device__ __half g_bh[MROWS*CEMB];     // h2
__device__ __half g_wh[768*CEMB];       // weights

__device__ __forceinline__ uint32_t smem_u32(const void* p) {
    uint32_t a;
    asm("{ .reg .u64 t; cvta.to.shared.u64 t, %1; cvt.u32.u64 %0, t; }" : "=r"(a) : "l"(p));
    return a;
}

#define LDSM_X4(r0, r1, r2, r3, addr) \
    asm volatile("ldmatrix.sync.aligned.m8n8.x4.shared.b16 {%0,%1,%2,%3}, [%4];" \
        : "=r"(r0), "=r"(r1), "=r"(r2), "=r"(r3) : "r"(addr))
#define LDSM_X2(r0, r1, addr) \
    asm volatile("ldmatrix.sync.aligned.m8n8.x2.shared.b16 {%0,%1}, [%2];" \
        : "=r"(r0), "=r"(r1) : "r"(addr))
#define MMA_F16(c, a, b) \
    asm volatile("mma.sync.aligned.m16n8k16.row.col.f32.f16.f16.f32 " \
        "{%0,%1,%2,%3}, {%4,%5,%6,%7}, {%8,%9}, {%0,%1,%2,%3};" \
        : "+f"((c)[0]), "+f"((c)[1]), "+f"((c)[2]), "+f"((c)[3]) \
        : "r"((a)[0]), "r"((a)[1]), "r"((a)[2]), "r"((a)[3]), "r"((b)[0]), "r"((b)[1]))

// ======================= fp16 HMMA GEMM, register-prefetch pipelined =======================
__global__ void __launch_bounds__(256, 2)
gemm_mma(const __half* __restrict__ A, const __half* __restrict__ W,
         float* __restrict__ C, __half* __restrict__ Ch,
         int M, int N, int K, int out_half)
{
    __shared__ __align__(1024) char sm[24576];
    char* AH = sm;            // 128*64*2 = 16KB
    char* WH = sm + 16384;    // 64*64*2  = 8KB

    const int tid = threadIdx.x, wid = tid >> 5, lane = tid & 31;
    const int wm = wid & 3, wn = wid >> 2;
    const int bm = blockIdx.y * 128, bn = blockIdx.x * 64;
    const uint32_t sAH = smem_u32(AH), sWH = smem_u32(WH);

    float acc[2][4][4];
    #pragma unroll
    for (int i = 0; i < 2; i++)
        #pragma unroll
        for (int j = 0; j < 4; j++)
            #pragma unroll
            for (int q = 0; q < 4; q++) acc[i][j][q] = 0.f;

    uint4 ra[4], rw[2];
    const int nkt = K >> 6;

    #pragma unroll
    for (int i = 0; i < 4; i++) {
        int idx = tid + i * 256, r = idx >> 3, q = idx & 7;
        ra[i] = *(const uint4*)(A + (size_t)(bm + r) * K + q * 8);
    }
    #pragma unroll
    for (int i = 0; i < 2; i++) {
        int idx = tid + i * 256, r = idx >> 3, q = idx & 7;
        rw[i] = *(const uint4*)(W + (size_t)(bn + r) * K + q * 8);
    }

    for (int kt = 0; kt < nkt; kt++) {
        #pragma unroll
        for (int i = 0; i < 4; i++) {
            int idx = tid + i * 256, r = idx >> 3, q = idx & 7;
            *(uint4*)(AH + r * 128 + ((q ^ (r & 7)) << 4)) = ra[i];
        }
        #pragma unroll
        for (int i = 0; i < 2; i++) {
            int idx = tid + i * 256, r = idx >> 3, q = idx & 7;
            *(uint4*)(WH + r * 128 + ((q ^ (r & 7)) << 4)) = rw[i];
        }
        __syncthreads();

        if (kt + 1 < nkt) {
            int k0 = (kt + 1) * 64;
            #pragma unroll
            for (int i = 0; i < 4; i++) {
                int idx = tid + i * 256, r = idx >> 3, q = idx & 7;
                ra[i] = *(const uint4*)(A + (size_t)(bm + r) * K + k0 + q * 8);
            }
            #pragma unroll
            for (int i = 0; i < 2; i++) {
                int idx = tid + i * 256, r = idx >> 3, q = idx & 7;
                rw[i] = *(const uint4*)(W + (size_t)(bn + r) * K + k0 + q * 8);
            }
        }

        #pragma unroll
        for (int ks = 0; ks < 4; ks++) {
            uint32_t ah[2][4], bh[4][2];
            #pragma unroll
            for (int mt = 0; mt < 2; mt++) {
                int r = wm * 32 + mt * 16 + (lane & 15);
                int c16 = ks * 2 + (lane >> 4);
                LDSM_X4(ah[mt][0], ah[mt][1], ah[mt][2], ah[mt][3],
                        sAH + r * 128 + ((c16 ^ (r & 7)) << 4));
            }
            #pragma unroll
            for (int nt = 0; nt < 4; nt++) {
                int rn = wn * 32 + nt * 8 + (lane & 7);
                int c16 = ks * 2 + ((lane >> 3) & 1);
                LDSM_X2(bh[nt][0], bh[nt][1],
                        sWH + rn * 128 + ((c16 ^ (rn & 7)) << 4));
            }
            #pragma unroll
            for (int mt = 0; mt < 2; mt++)
                #pragma unroll
                for (int nt = 0; nt < 4; nt++)
                    MMA_F16(acc[mt][nt], ah[mt], bh[nt]);
        }
        __syncthreads();
    }

    if (!out_half) {
        #pragma unroll
        for (int mt = 0; mt < 2; mt++) {
            int row = bm + wm * 32 + mt * 16 + (lane >> 2);
            #pragma unroll
            for (int nt = 0; nt < 4; nt++) {
                int col = bn + wn * 32 + nt * 8 + (lane & 3) * 2;
                *(float2*)(C + (size_t)row * N + col)       = make_float2(acc[mt][nt][0], acc[mt][nt][1]);
                *(float2*)(C + (size_t)(row + 8) * N + col) = make_float2(acc[mt][nt][2], acc[mt][nt][3]);
            }
        }
    } else {
        #pragma unroll
        for (int mt = 0; mt < 2; mt++) {
            int row = bm + wm * 32 + mt * 16 + (lane >> 2);
            #pragma unroll
            for (int nt = 0; nt < 4; nt++) {
                int col = bn + wn * 32 + nt * 8 + (lane & 3) * 2;
                #pragma unroll
                for (int hh = 0; hh < 2; hh++) {
                    uint32_t hp;
                    asm("cvt.rn.f16x2.f32 %0, %1, %2;" : "=r"(hp)
                        : "f"(acc[mt][nt][hh*2+1]), "f"(acc[mt][nt][hh*2+0]));
                    *(uint32_t*)(Ch + (size_t)(row + hh*8) * N + col) = hp;
                }
            }
        }
    }
}

// ---------------- weight convert: fp32 -> fp16 ----------------
__global__ void wcvt_k(const float* __restrict__ src, int n4) {
    int idx = blockIdx.x * blockDim.x + threadIdx.x;
    if (idx >= n4) return;
    float4 v = ((const float4*)src)[idx];
    uint32_t p0, p1;
    asm("cvt.rn.f16x2.f32 %0, %1, %2;" : "=r"(p0) : "f"(v.y), "f"(v.x));
    asm("cvt.rn.f16x2.f32 %0, %1, %2;" : "=r"(p1) : "f"(v.w), "f"(v.z));
    ((uint2*)g_wh)[idx] = make_uint2(p0, p1);
}

// ---------------- transpose (B,C,L) -> (B,L,C), fp32 + fp16 ----------------
__global__ void transpose_k(const float* __restrict__ x) {
    __shared__ float t[32][33];
    int b = blockIdx.z;
    int l0 = blockIdx.x * 32, c0 = blockIdx.y * 32;
    int tx = threadIdx.x, ty = threadIdx.y;
    #pragma unroll
    for (int j = ty; j < 32; j += 8)
        t[j][tx] = x[((b*CEMB) + (c0 + j)) * LLEN + l0 + tx];
    __syncthreads();
    #pragma unroll
    for (int j = ty; j < 32; j += 8) {
        float v = t[tx][j];
        size_t idx = ((size_t)(b*LLEN) + (l0 + j)) * CEMB + c0 + tx;
        g_xh[idx] = v;
        g_ah[idx] = __float2half_rn(v);
    }
}

// ---------------- A structure prep ----------------
__global__ void prepA_k(const float* __restrict__ A_log) {
    int mix = blockIdx.x;
    int d = threadIdx.x;
    if (d == 0) g_slow[mix] = 0;
    __syncthreads();
    const float* al = A_log + mix * DIN * 4;
    float a[4];
    #pragma unroll
    for (int s = 0; s < 4; s++) {
        a[s] = -expf(al[d*4 + s]);
        g_A[(mix*DIN + d)*4 + s] = a[s];
    }
    bool ok = true;
    #pragma unroll
    for (int s = 0; s < 4; s++) {
        float want = (float)(s + 1) * a[0];
        if (fabsf(a[s] - want) > 1e-5f * fabsf(a[s]) + 1e-7f) ok = false;
    }
    if (!ok) atomicExch(&g_slow[mix], 1);
}

// ---------------- Uf = U_w @ Wout2 ----------------
__global__ void uf_k(const float* __restrict__ U, const float* __restrict__ Wout2) {
    __shared__ float Ush[4*CEMB];
    int k = threadIdx.x;
    for (int i = k; i < 4*CEMB; i += DIN) Ush[i] = U[i];
    __syncthreads();
    float acc0 = 0.f, acc1 = 0.f, acc2 = 0.f, acc3 = 0.f;
    for (int c = 0; c < CEMB; c++) {
        float w = Wout2[(size_t)c * DIN + k];
        acc0 = fmaf(Ush[0*CEMB + c], w, acc0);
        acc1 = fmaf(Ush[1*CEMB + c], w, acc1);
        acc2 = fmaf(Ush[2*CEMB + c], w, acc2);
        acc3 = fmaf(Ush[3*CEMB + c], w, acc3);
    }
    g_Uf[0*DIN + k] = acc0;
    g_Uf[1*DIN + k] = acc1;
    g_Uf[2*DIN + k] = acc2;
    g_Uf[3*DIN + k] = acc3;
}

// ---------------- depthwise causal conv + silu, rolling window ----------------
__global__ void __launch_bounds__(256)
conv_k(const float* __restrict__ w, const float* __restrict__ bias) {
    int idx = blockIdx.x * blockDim.x + threadIdx.x;
    if (idx >= (MROWS/8) * (DIN/4)) return;
    int d4 = idx % (DIN/4);
    int m8 = idx / (DIN/4);
    int d  = d4 * 4;
    int bl = m8 * 8;
    int l  = bl % LLEN;

    float4 wv0 = *(const float4*)(w + (d+0)*4);
    float4 wv1 = *(const float4*)(w + (d+1)*4);
    float4 wv2 = *(const float4*)(w + (d+2)*4);
    float4 wv3 = *(const float4*)(w + (d+3)*4);
    float4 bv  = *(const float4*)(bias + d);

    const float* p = g_xz + (size_t)bl * (2*DIN) + d;
    float* po = g_xa + (size_t)bl * DIN + d;
    float4 x1 = make_float4(0,0,0,0), x2 = x1, x3 = x1;
    if (l) {
        x3 = *(const float4*)(p - 3*2*DIN);
        x2 = *(const float4*)(p - 2*2*DIN);
        x1 = *(const float4*)(p - 2*DIN);
    }
    #pragma unroll
    for (int j = 0; j < 8; j++) {
        float4 x0 = *(const float4*)(p + j*2*DIN);
        float4 acc = bv;
        acc.x = fmaf(wv0.x, x3.x, acc.x); acc.y = fmaf(wv1.x, x3.y, acc.y);
        acc.z = fmaf(wv2.x, x3.z, acc.z); acc.w = fmaf(wv3.x, x3.w, acc.w);
        acc.x = fmaf(wv0.y, x2.x, acc.x); acc.y = fmaf(wv1.y, x2.y, acc.y);
        acc.z = fmaf(wv2.y, x2.z, acc.z); acc.w = fmaf(wv3.y, x2.w, acc.w);
        acc.x = fmaf(wv0.z, x1.x, acc.x); acc.y = fmaf(wv1.z, x1.y, acc.y);
        acc.z = fmaf(wv2.z, x1.z, acc.z); acc.w = fmaf(wv3.z, x1.w, acc.w);
        acc.x = fmaf(wv0.w, x0.x, acc.x); acc.y = fmaf(wv1.w, x0.y, acc.y);
        acc.z = fmaf(wv2.w, x0.z, acc.z); acc.w = fmaf(wv3.w, x0.w, acc.w);
        float4 s;
        s.x = __fdividef(acc.x, 1.f + __expf(-acc.x));
        s.y = __fdividef(acc.y, 1.f + __expf(-acc.y));
        s.z = __fdividef(acc.z, 1.f + __expf(-acc.z));
        s.w = __fdividef(acc.w, 1.f + __expf(-acc.w));
        *(float4*)(po + j*DIN) = s;
        x3 = x2; x2 = x1; x1 = x0;
    }
}

// ---------------- x_proj ----------------
__global__ void __launch_bounds__(256)
xproj_k(const float* __restrict__ W) {
    __shared__ __align__(16) float Wsh[XD * DIN];
    for (int i = threadIdx.x; i < XD*DIN; i += 256) Wsh[i] = W[i];
    __syncthreads();
    int warp = threadIdx.x >> 5, lane = threadIdx.x & 31;
    int m0 = blockIdx.x * 32;
    for (int r = warp; r < 32; r += 8) {
        int m = m0 + r;
        const float4* ar = (const float4*)(g_xa + (size_t)m * DIN);
        float acc[XD];
        #pragma unroll
        for (int n = 0; n < XD; n++) acc[n] = 0.f;
        #pragma unroll
        for (int it = 0; it < 3; it++) {
            int k4 = lane + it * 32;
            float4 a = ar[k4];
            #pragma unroll
            for (int n = 0; n < XD; n++) {
                const float4 wv = *(const float4*)(Wsh + n*DIN + k4*4);
                acc[n] = fmaf(a.x, wv.x, fmaf(a.y, wv.y, fmaf(a.z, wv.z, fmaf(a.w, wv.w, acc[n]))));
            }
        }
        float myv = 0.f;
        #pragma unroll
        for (int n = 0; n < XD; n++) {
            float v = acc[n];
            #pragma unroll
            for (int off = 16; off > 0; off >>= 1)
                v += __shfl_xor_sync(0xffffffffu, v, off);
            if (lane == n) myv = v;
        }
        if (lane < DTR) g_xdbl[(size_t)m*DTR + lane] = myv;
        else if (lane < XD) g_bc[(size_t)m*8 + lane - DTR] = myv;
    }
}

// ---------------- scan pass 1 ----------------
__global__ void scan1_k(const float* __restrict__ dtw, const float* __restrict__ dtb, int mix) {
    __shared__ float Bsm[LC][4];
    __shared__ float Xd[LC][DTR];
    int chunk = blockIdx.x, b = blockIdx.y, d = threadIdx.x;
    int l0 = chunk * LC;
    if (threadIdx.x < LC*4) {
        int l = threadIdx.x >> 2, s = threadIdx.x & 3;
        Bsm[l][s] = g_bc[((size_t)(b*LLEN + l0 + l))*8 + s];
    }
    {
        int l = threadIdx.x / DTR, r = threadIdx.x - l*DTR;
        Xd[l][r] = g_xdbl[((size_t)(b*LLEN + l0 + l))*DTR + r];
    }
    __syncthreads();
    int slow = g_slow[mix];
    const float* Ab = g_A + (mix*DIN + d)*4;
    float Av0 = Ab[0], Av1 = Ab[1], Av2 = Ab[2], Av3 = Ab[3];
    const float4* w4 = (const float4*)(dtw + d * DTR);
    float4 dw0 = w4[0], dw1 = w4[1], dw2 = w4[2];
    float pb = dtb[d];
    float h0 = 0.f, h1 = 0.f, h2 = 0.f, h3 = 0.f, sd = 0.f;
    const float* pa = g_xa + (size_t)(b*LLEN + l0)*DIN + d;
    #pragma unroll 4
    for (int l = 0; l < LC; l++) {
        float xav = pa[l*DIN];
        const float* xr = Xd[l];
        float p = pb;
        p = fmaf(xr[0], dw0.x, p);  p = fmaf(xr[1], dw0.y, p);
        p = fmaf(xr[2], dw0.z, p);  p = fmaf(xr[3], dw0.w, p);
        p = fmaf(xr[4], dw1.x, p);  p = fmaf(xr[5], dw1.y, p);
        p = fmaf(xr[6], dw1.z, p);  p = fmaf(xr[7], dw1.w, p);
        p = fmaf(xr[8], dw2.x, p);  p = fmaf(xr[9], dw2.y, p);
        p = fmaf(xr[10], dw2.z, p); p = fmaf(xr[11], dw2.w, p);
        float dtv = (p > 20.f) ? p : __logf(1.f + __expf(p));
        float dbu = dtv * xav;
        sd += dtv;
        float b0 = Bsm[l][0], b1 = Bsm[l][1], b2 = Bsm[l][2], b3 = Bsm[l][3];
        if (!slow) {
            float e = __expf(Av0 * dtv);
            float q = e;
            h0 = fmaf(q, h0, dbu*b0); q *= e;
            h1 = fmaf(q, h1, dbu*b1); q *= e;
            h2 = fmaf(q, h2, dbu*b2); q *= e;
            h3 = fmaf(q, h3, dbu*b3);
        } else {
            h0 = fmaf(__expf(dtv*Av0), h0, dbu*b0);
            h1 = fmaf(__expf(dtv*Av1), h1, dbu*b1);
            h2 = fmaf(__expf(dtv*Av2), h2, dbu*b2);
            h3 = fmaf(__expf(dtv*Av3), h3, dbu*b3);
        }
    }
    int o = ((b*DIN) + d)*NC + chunk;
    ((float4*)g_hpart)[o] = make_float4(h0, h1, h2, h3);
    g_sumdt[o] = sd;
}

// ---------------- scan pass 2 ----------------
__global__ void scan2_k(int mix) {
    int t = blockIdx.x * blockDim.x + threadIdx.x;
    if (t >= BB*DIN) return;
    int d = t % DIN;
    const float* Ab = g_A + (mix*DIN + d)*4;
    float Av0 = Ab[0], Av1 = Ab[1], Av2 = Ab[2], Av3 = Ab[3];
    float H0 = 0.f, H1 = 0.f, H2 = 0.f, H3 = 0.f;
    for (int c = 0; c < NC; c++) {
        int o = t*NC + c;
        ((float4*)g_Hinit)[o] = make_float4(H0, H1, H2, H3);
        float4 hp = ((const float4*)g_hpart)[o];
        float sd = g_sumdt[o];
        H0 = fmaf(__expf(Av0*sd), H0, hp.x);
        H1 = fmaf(__expf(Av1*sd), H1, hp.y);
        H2 = fmaf(__expf(Av2*sd), H2, hp.z);
        H3 = fmaf(__expf(Av3*sd), H3, hp.w);
    }
}

// ---------------- scan pass 3 ----------------
__global__ void scan3_k(const float* __restrict__ dtw, const float* __restrict__ dtb,
                        const float* __restrict__ Dw, int mix, int write_half) {
    __shared__ float Bsm[LC][4];
    __shared__ float Csm[LC][4];
    __shared__ float Xd[LC][DTR];
    int chunk = blockIdx.x, b = blockIdx.y, d = threadIdx.x;
    int l0 = chunk * LC;
    if (threadIdx.x < LC*8) {
        int l = threadIdx.x >> 3, s = threadIdx.x & 7;
        float v = g_bc[((size_t)(b*LLEN + l0 + l))*8 + s];
        if (s < 4) Bsm[l][s] = v; else Csm[l][s-4] = v;
    }
    {
        int l = threadIdx.x / DTR, r = threadIdx.x - l*DTR;
        Xd[l][r] = g_xdbl[((size_t)(b*LLEN + l0 + l))*DTR + r];
    }
    __syncthreads();
    int slow = g_slow[mix];
    const float* Ab = g_A + (mix*DIN + d)*4;
    float Av0 = Ab[0], Av1 = Ab[1], Av2 = Ab[2], Av3 = Ab[3];
    const float4* w4 = (const float4*)(dtw + d * DTR);
    float4 dw0 = w4[0], dw1 = w4[1], dw2 = w4[2];
    float pb = dtb[d];
    float Dd = Dw[d];
    int o = ((b*DIN) + d)*NC + chunk;
    float4 Hi = ((const float4*)g_Hinit)[o];
    float h0 = Hi.x, h1 = Hi.y, h2 = Hi.z, h3 = Hi.w;
    size_t base = (size_t)(b*LLEN + l0)*DIN + d;
    const float* pa = g_xa + base;
    const float* pz = g_xz + (size_t)(b*LLEN + l0)*(2*DIN) + DIN + d;
    #pragma unroll 4
    for (int l = 0; l < LC; l++) {
        float xav = pa[l*DIN];
        const float* xr = Xd[l];
        float p = pb;
        p = fmaf(xr[0], dw0.x, p);  p = fmaf(xr[1], dw0.y, p);
        p = fmaf(xr[2], dw0.z, p);  p = fmaf(xr[3], dw0.w, p);
        p = fmaf(xr[4], dw1.x, p);  p = fmaf(xr[5], dw1.y, p);
        p = fmaf(xr[6], dw1.z, p);  p = fmaf(xr[7], dw1.w, p);
        p = fmaf(xr[8], dw2.x, p);  p = fmaf(xr[9], dw2.y, p);
        p = fmaf(xr[10], dw2.z, p); p = fmaf(xr[11], dw2.w, p);
        float dtv = (p > 20.f) ? p : __logf(1.f + __expf(p));
        float dbu = dtv * xav;
        float b0 = Bsm[l][0], b1 = Bsm[l][1], b2 = Bsm[l][2], b3 = Bsm[l][3];
        if (!slow) {
            float e = __expf(Av0 * dtv);
            float q = e;
            h0 = fmaf(q, h0, dbu*b0); q *= e;
            h1 = fmaf(q, h1, dbu*b1); q *= e;
            h2 = fmaf(q, h2, dbu*b2); q *= e;
            h3 = fmaf(q, h3, dbu*b3);
        } else {
            h0 = fmaf(__expf(dtv*Av0), h0, dbu*b0);
            h1 = fmaf(__expf(dtv*Av1), h1, dbu*b1);
            h2 = fmaf(__expf(dtv*Av2), h2, dbu*b2);
            h3 = fmaf(__expf(dtv*Av3), h3, dbu*b3);
        }
        float y = h0*Csm[l][0] + h1*Csm[l][1] + h2*Csm[l][2] + h3*Csm[l][3];
        y = fmaf(xav, Dd, y);
        float zv = pz[l*2*DIN];
        float zs = __fdividef(zv, 1.f + __expf(-zv));
        float yo = y * zs;
        if (write_half) {
            g_ah[base + l*DIN] = __float2half_rn(yo);
        } else {
            g_y[base + l*DIN] = yo;
        }
    }
}

// ---------------- final ----------------
__global__ void final_k(const float* __restrict__ V,
                        const float* __restrict__ lng, const float* __restrict__ lnb,
                        float* __restrict__ out)
{
    __shared__ __align__(16) float Ufs[4*DIN];
    __shared__ float Vsh[CEMB*4];
    __shared__ float u[32][4];
    __shared__ float vs[32][193];
    __shared__ float mu[32], rsd[32];
    int b = blockIdx.y;
    int l0 = blockIdx.x * 32;
    int tid = threadIdx.x;
    for (int i = tid; i < 4*DIN; i += 256) Ufs[i] = g_Uf[i];
    for (int i = tid; i < 4*CEMB; i += 256) Vsh[i] = V[i];
    __syncthreads();
    if (tid < 128) {
        int p = tid >> 2, r = tid & 3;
        const float4* yr = (const float4*)(g_y + ((size_t)(b*LLEN) + l0 + p)*DIN);
        const float4* uf = (const float4*)(Ufs + r*DIN);
        float a = 0.f;
        #pragma unroll 8
        for (int c = 0; c < DIN/4; c++) {
            float4 yv = yr[c];
            float4 wv = uf[c];
            a = fmaf(yv.x, wv.x, fmaf(yv.y, wv.y, fmaf(yv.z, wv.z, fmaf(yv.w, wv.w, a))));
        }
        u[p][r] = a;
    }
    __syncthreads();
    for (int i = tid; i < 32*CEMB; i += 256) {
        int p = i / CEMB, c = i % CEMB;
        float v = g_xh[((size_t)(b*LLEN) + l0 + p)*CEMB + c];
        v = fmaf(Vsh[c*4+0], u[p][0], v);
        v = fmaf(Vsh[c*4+1], u[p][1], v);
        v = fmaf(Vsh[c*4+2], u[p][2], v);
        v = fmaf(Vsh[c*4+3], u[p][3], v);
        vs[p][c] = v;
    }
    __syncthreads();
    int warp = tid >> 5, lane = tid & 31;
    #pragma unroll
    for (int pp = 0; pp < 4; pp++) {
        int p = warp*4 + pp;
        float s = 0.f, ss = 0.f;
        for (int c = lane; c < CEMB; c += 32) {
            float v = vs[p][c];
            s += v; ss = fmaf(v, v, ss);
        }
        #pragma unroll
        for (int off = 16; off > 0; off >>= 1) {
            s  += __shfl_xor_sync(0xffffffffu, s, off);
            ss += __shfl_xor_sync(0xffffffffu, ss, off);
        }
        if (lane == 0) {
            float m = s * (1.f/CEMB);
            mu[p] = m;
            rsd[p] = rsqrtf(ss * (1.f/CEMB) - m*m + 1e-5f);
        }
    }
    __syncthreads();
    for (int c = warp; c < CEMB; c += 8) {
        int p = lane;
        float v = (vs[p][c] - mu[p]) * rsd[p] * lng[c] + lnb[c];
        out[((size_t)(b*CEMB) + c)*LLEN + l0 + lane] = v;
    }
}

// ---------------- launch ----------------
extern "C" void kernel_launch(void* const* d_in, const int* in_sizes, int n_in,
                              void* d_out, int out_size)
{
    const float* x         = (const float*)d_in[0];
    const float* in_proj_w = (const float*)d_in[1];
    const float* conv_w    = (const float*)d_in[2];
    const float* conv_b    = (const float*)d_in[3];
    const float* x_proj_w  = (const float*)d_in[4];
    const float* dt_proj_w = (const float*)d_in[5];
    const float* dt_proj_b = (const float*)d_in[6];
    const float* A_log     = (const float*)d_in[7];
    const float* Dw        = (const float*)d_in[8];
    const float* out_proj_w= (const float*)d_in[9];
    const float* U_w       = (const float*)d_in[10];
    const float* V_w       = (const float*)d_in[11];
    const float* ln_g      = (const float*)d_in[12];
    const float* ln_b      = (const float*)d_in[13];
    float* out = (float*)d_out;

    float* g_xz_p;  cudaGetSymbolAddress((void**)&g_xz_p,  g_xz);
    __half *ah_p, *bh_p, *wh_p;
    cudaGetSymbolAddress((void**)&ah_p, g_ah);
    cudaGetSymbolAddress((void**)&bh_p, g_bh);
    cudaGetSymbolAddress((void**)&wh_p, g_wh);

    transpose_k<<<dim3(LLEN/32, CEMB/32, BB), dim3(32, 8)>>>(x);
    prepA_k<<<2, DIN>>>(A_log);
    uf_k<<<1, DIN>>>(U_w, out_proj_w + (size_t)CEMB*DIN);

    for (int mix = 0; mix < 2; mix++) {
        const float* dtw = dt_proj_w + (size_t)mix*DIN*DTR;
        const float* dtb = dt_proj_b + mix*DIN;
        const __half* Ain = (mix == 0) ? ah_p : bh_p;

        wcvt_k<<<(2*DIN*CEMB/4 + 255)/256, 256>>>(in_proj_w + (size_t)mix*2*DIN*CEMB, 2*DIN*CEMB/4);
        gemm_mma<<<dim3((2*DIN)/64, MROWS/128), 256>>>(
            Ain, wh_p, g_xz_p, nullptr, MROWS, 2*DIN, CEMB, 0);
        conv_k<<<((MROWS/8)*(DIN/4) + 255)/256, 256>>>(conv_w + mix*DIN*4, conv_b + mix*DIN);
        xproj_k<<<MROWS/32, 256>>>(x_proj_w + (size_t)mix*XD*DIN);
        scan1_k<<<dim3(NC, BB), DIN>>>(dtw, dtb, mix);
        scan2_k<<<(BB*DIN + 255)/256, 256>>>(mix);
        scan3_k<<<dim3(NC, BB), DIN>>>(dtw, dtb, Dw + mix*DIN, mix, mix == 0 ? 1 : 0);
        if (mix == 0) {
            wcvt_k<<<(CEMB*DIN/4 + 255)/256, 256>>>(out_proj_w, CEMB*DIN/4);
            gemm_mma<<<dim3(CEMB/64, MROWS/128), 256>>>(
                ah_p, wh_p, nullptr, bh_p, MROWS, CEMB, DIN, 1);
        }
    }

    final_k<<<dim3(LLEN/32, BB), 256>>>(V_w, ln_g, ln_b, out);
}

// round 15
// speedup vs baseline: 1.2636x; 1.0670x over previous
#include <cuda_runtime.h>
#include <cuda_fp16.h>
#include <cstdint>

#define BB   8
#define LLEN 4096
#define CEMB 192
#define DIN  384
#define XD   20
#define DTR  12
#define NC   128
#define LC   32
#define MROWS (BB*LLEN)

// ---------------- scratch ----------------
__device__ float g_xh  [MROWS*CEMB];
__device__ __half g_xzh[MROWS*2*DIN];     // in_proj output (fp16)
__device__ __half g_xah[MROWS*DIN];       // conv+silu output (fp16)
__device__ float g_xdbl[MROWS*DTR];
__device__ float g_bc  [MROWS*8];
__device__ float g_y   [MROWS*DIN];
__device__ float g_hpart[BB*DIN*NC*4];
__device__ float g_sumdt[BB*DIN*NC];
__device__ float g_Hinit[BB*DIN*NC*4];
__device__ float g_A[2*DIN*4];
__device__ int   g_slow[2];
__device__ float g_Uf[4*DIN];
__device__ __half g_ah[MROWS*DIN];        // xh then y (GEMM A operand)
__device__ __half g_bh[MROWS*CEMB];       // h2
__device__ __half g_wh[2*768*CEMB + CEMB*DIN];  // weights: inproj0 | inproj1 | outproj0

__device__ __forceinline__ uint32_t smem_u32(const void* p) {
    uint32_t a;
    asm("{ .reg .u64 t; cvta.to.shared.u64 t, %1; cvt.u32.u64 %0, t; }" : "=r"(a) : "l"(p));
    return a;
}
__device__ __forceinline__ float4 ld4h(const __half* p) {
    uint2 u = *(const uint2*)p;
    __half2 h0 = *(__half2*)&u.x, h1 = *(__half2*)&u.y;
    float2 f0 = __half22float2(h0), f1 = __half22float2(h1);
    return make_float4(f0.x, f0.y, f1.x, f1.y);
}
__device__ __forceinline__ void st4h(__half* p, float4 v) {
    uint32_t p0, p1;
    asm("cvt.rn.f16x2.f32 %0, %1, %2;" : "=r"(p0) : "f"(v.y), "f"(v.x));
    asm("cvt.rn.f16x2.f32 %0, %1, %2;" : "=r"(p1) : "f"(v.w), "f"(v.z));
    *(uint2*)p = make_uint2(p0, p1);
}

#define LDSM_X4(r0, r1, r2, r3, addr) \
    asm volatile("ldmatrix.sync.aligned.m8n8.x4.shared.b16 {%0,%1,%2,%3}, [%4];" \
        : "=r"(r0), "=r"(r1), "=r"(r2), "=r"(r3) : "r"(addr))
#define LDSM_X2(r0, r1, addr) \
    asm volatile("ldmatrix.sync.aligned.m8n8.x2.shared.b16 {%0,%1}, [%2];" \
        : "=r"(r0), "=r"(r1) : "r"(addr))
#define MMA_F16(c, a, b) \
    asm volatile("mma.sync.aligned.m16n8k16.row.col.f32.f16.f16.f32 " \
        "{%0,%1,%2,%3}, {%4,%5,%6,%7}, {%8,%9}, {%0,%1,%2,%3};" \
        : "+f"((c)[0]), "+f"((c)[1]), "+f"((c)[2]), "+f"((c)[3]) \
        : "r"((a)[0]), "r"((a)[1]), "r"((a)[2]), "r"((a)[3]), "r"((b)[0]), "r"((b)[1]))

// ======================= fp16 HMMA GEMM, register-prefetch pipelined =======================
__global__ void __launch_bounds__(256, 2)
gemm_mma(const __half* __restrict__ A, const __half* __restrict__ W,
         float* __restrict__ C, __half* __restrict__ Ch,
         int M, int N, int K, int out_half)
{
    __shared__ __align__(1024) char sm[24576];
    char* AH = sm;
    char* WH = sm + 16384;

    const int tid = threadIdx.x, wid = tid >> 5, lane = tid & 31;
    const int wm = wid & 3, wn = wid >> 2;
    const int bm = blockIdx.y * 128, bn = blockIdx.x * 64;
    const uint32_t sAH = smem_u32(AH), sWH = smem_u32(WH);

    float acc[2][4][4];
    #pragma unroll
    for (int i = 0; i < 2; i++)
        #pragma unroll
        for (int j = 0; j < 4; j++)
            #pragma unroll
            for (int q = 0; q < 4; q++) acc[i][j][q] = 0.f;

    uint4 ra[4], rw[2];
    const int nkt = K >> 6;

    #pragma unroll
    for (int i = 0; i < 4; i++) {
        int idx = tid + i * 256, r = idx >> 3, q = idx & 7;
        ra[i] = *(const uint4*)(A + (size_t)(bm + r) * K + q * 8);
    }
    #pragma unroll
    for (int i = 0; i < 2; i++) {
        int idx = tid + i * 256, r = idx >> 3, q = idx & 7;
        rw[i] = *(const uint4*)(W + (size_t)(bn + r) * K + q * 8);
    }

    for (int kt = 0; kt < nkt; kt++) {
        #pragma unroll
        for (int i = 0; i < 4; i++) {
            int idx = tid + i * 256, r = idx >> 3, q = idx & 7;
            *(uint4*)(AH + r * 128 + ((q ^ (r & 7)) << 4)) = ra[i];
        }
        #pragma unroll
        for (int i = 0; i < 2; i++) {
            int idx = tid + i * 256, r = idx >> 3, q = idx & 7;
            *(uint4*)(WH + r * 128 + ((q ^ (r & 7)) << 4)) = rw[i];
        }
        __syncthreads();

        if (kt + 1 < nkt) {
            int k0 = (kt + 1) * 64;
            #pragma unroll
            for (int i = 0; i < 4; i++) {
                int idx = tid + i * 256, r = idx >> 3, q = idx & 7;
                ra[i] = *(const uint4*)(A + (size_t)(bm + r) * K + k0 + q * 8);
            }
            #pragma unroll
            for (int i = 0; i < 2; i++) {
                int idx = tid + i * 256, r = idx >> 3, q = idx & 7;
                rw[i] = *(const uint4*)(W + (size_t)(bn + r) * K + k0 + q * 8);
            }
        }

        #pragma unroll
        for (int ks = 0; ks < 4; ks++) {
            uint32_t ah[2][4], bh[4][2];
            #pragma unroll
            for (int mt = 0; mt < 2; mt++) {
                int r = wm * 32 + mt * 16 + (lane & 15);
                int c16 = ks * 2 + (lane >> 4);
                LDSM_X4(ah[mt][0], ah[mt][1], ah[mt][2], ah[mt][3],
                        sAH + r * 128 + ((c16 ^ (r & 7)) << 4));
            }
            #pragma unroll
            for (int nt = 0; nt < 4; nt++) {
                int rn = wn * 32 + nt * 8 + (lane & 7);
                int c16 = ks * 2 + ((lane >> 3) & 1);
                LDSM_X2(bh[nt][0], bh[nt][1],
                        sWH + rn * 128 + ((c16 ^ (rn & 7)) << 4));
            }
            #pragma unroll
            for (int mt = 0; mt < 2; mt++)
                #pragma unroll
                for (int nt = 0; nt < 4; nt++)
                    MMA_F16(acc[mt][nt], ah[mt], bh[nt]);
        }
        __syncthreads();
    }

    if (!out_half) {
        #pragma unroll
        for (int mt = 0; mt < 2; mt++) {
            int row = bm + wm * 32 + mt * 16 + (lane >> 2);
            #pragma unroll
            for (int nt = 0; nt < 4; nt++) {
                int col = bn + wn * 32 + nt * 8 + (lane & 3) * 2;
                *(float2*)(C + (size_t)row * N + col)       = make_float2(acc[mt][nt][0], acc[mt][nt][1]);
                *(float2*)(C + (size_t)(row + 8) * N + col) = make_float2(acc[mt][nt][2], acc[mt][nt][3]);
            }
        }
    } else {
        #pragma unroll
        for (int mt = 0; mt < 2; mt++) {
            int row = bm + wm * 32 + mt * 16 + (lane >> 2);
            #pragma unroll
            for (int nt = 0; nt < 4; nt++) {
                int col = bn + wn * 32 + nt * 8 + (lane & 3) * 2;
                #pragma unroll
                for (int hh = 0; hh < 2; hh++) {
                    uint32_t hp;
                    asm("cvt.rn.f16x2.f32 %0, %1, %2;" : "=r"(hp)
                        : "f"(acc[mt][nt][hh*2+1]), "f"(acc[mt][nt][hh*2+0]));
                    *(uint32_t*)(Ch + (size_t)(row + hh*8) * N + col) = hp;
                }
            }
        }
    }
}

// ---------------- weight convert: fp32 -> fp16 at offset ----------------
__global__ void wcvt_k(const float* __restrict__ src, int n4, int dst4) {
    int idx = blockIdx.x * blockDim.x + threadIdx.x;
    if (idx >= n4) return;
    float4 v = ((const float4*)src)[idx];
    uint32_t p0, p1;
    asm("cvt.rn.f16x2.f32 %0, %1, %2;" : "=r"(p0) : "f"(v.y), "f"(v.x));
    asm("cvt.rn.f16x2.f32 %0, %1, %2;" : "=r"(p1) : "f"(v.w), "f"(v.z));
    ((uint2*)g_wh)[dst4 + idx] = make_uint2(p0, p1);
}

// ---------------- transpose (B,C,L) -> (B,L,C), fp32 + fp16 ----------------
__global__ void transpose_k(const float* __restrict__ x) {
    __shared__ float t[32][33];
    int b = blockIdx.z;
    int l0 = blockIdx.x * 32, c0 = blockIdx.y * 32;
    int tx = threadIdx.x, ty = threadIdx.y;
    #pragma unroll
    for (int j = ty; j < 32; j += 8)
        t[j][tx] = x[((b*CEMB) + (c0 + j)) * LLEN + l0 + tx];
    __syncthreads();
    #pragma unroll
    for (int j = ty; j < 32; j += 8) {
        float v = t[tx][j];
        size_t idx = ((size_t)(b*LLEN) + (l0 + j)) * CEMB + c0 + tx;
        g_xh[idx] = v;
        g_ah[idx] = __float2half_rn(v);
    }
}

// ---------------- A structure prep ----------------
__global__ void prepA_k(const float* __restrict__ A_log) {
    int mix = blockIdx.x;
    int d = threadIdx.x;
    if (d == 0) g_slow[mix] = 0;
    __syncthreads();
    const float* al = A_log + mix * DIN * 4;
    float a[4];
    #pragma unroll
    for (int s = 0; s < 4; s++) {
        a[s] = -expf(al[d*4 + s]);
        g_A[(mix*DIN + d)*4 + s] = a[s];
    }
    bool ok = true;
    #pragma unroll
    for (int s = 0; s < 4; s++) {
        float want = (float)(s + 1) * a[0];
        if (fabsf(a[s] - want) > 1e-5f * fabsf(a[s]) + 1e-7f) ok = false;
    }
    if (!ok) atomicExch(&g_slow[mix], 1);
}

// ---------------- Uf = U_w @ Wout2 ----------------
__global__ void uf_k(const float* __restrict__ U, const float* __restrict__ Wout2) {
    __shared__ float Ush[4*CEMB];
    int k = threadIdx.x;
    for (int i = k; i < 4*CEMB; i += DIN) Ush[i] = U[i];
    __syncthreads();
    float acc0 = 0.f, acc1 = 0.f, acc2 = 0.f, acc3 = 0.f;
    for (int c = 0; c < CEMB; c++) {
        float w = Wout2[(size_t)c * DIN + k];
        acc0 = fmaf(Ush[0*CEMB + c], w, acc0);
        acc1 = fmaf(Ush[1*CEMB + c], w, acc1);
        acc2 = fmaf(Ush[2*CEMB + c], w, acc2);
        acc3 = fmaf(Ush[3*CEMB + c], w, acc3);
    }
    g_Uf[0*DIN + k] = acc0;
    g_Uf[1*DIN + k] = acc1;
    g_Uf[2*DIN + k] = acc2;
    g_Uf[3*DIN + k] = acc3;
}

// ---------------- depthwise causal conv + silu, rolling window, fp16 IO ----------------
__global__ void __launch_bounds__(256)
conv_k(const float* __restrict__ w, const float* __restrict__ bias) {
    int idx = blockIdx.x * blockDim.x + threadIdx.x;
    if (idx >= (MROWS/8) * (DIN/4)) return;
    int d4 = idx % (DIN/4);
    int m8 = idx / (DIN/4);
    int d  = d4 * 4;
    int bl = m8 * 8;
    int l  = bl % LLEN;

    float4 wv0 = *(const float4*)(w + (d+0)*4);
    float4 wv1 = *(const float4*)(w + (d+1)*4);
    float4 wv2 = *(const float4*)(w + (d+2)*4);
    float4 wv3 = *(const float4*)(w + (d+3)*4);
    float4 bv  = *(const float4*)(bias + d);

    const __half* p = g_xzh + (size_t)bl * (2*DIN) + d;
    __half* po = g_xah + (size_t)bl * DIN + d;
    float4 x1 = make_float4(0,0,0,0), x2 = x1, x3 = x1;
    if (l) {
        x3 = ld4h(p - 3*2*DIN);
        x2 = ld4h(p - 2*2*DIN);
        x1 = ld4h(p - 2*DIN);
    }
    #pragma unroll
    for (int j = 0; j < 8; j++) {
        float4 x0 = ld4h(p + j*2*DIN);
        float4 acc = bv;
        acc.x = fmaf(wv0.x, x3.x, acc.x); acc.y = fmaf(wv1.x, x3.y, acc.y);
        acc.z = fmaf(wv2.x, x3.z, acc.z); acc.w = fmaf(wv3.x, x3.w, acc.w);
        acc.x = fmaf(wv0.y, x2.x, acc.x); acc.y = fmaf(wv1.y, x2.y, acc.y);
        acc.z = fmaf(wv2.y, x2.z, acc.z); acc.w = fmaf(wv3.y, x2.w, acc.w);
        acc.x = fmaf(wv0.z, x1.x, acc.x); acc.y = fmaf(wv1.z, x1.y, acc.y);
        acc.z = fmaf(wv2.z, x1.z, acc.z); acc.w = fmaf(wv3.z, x1.w, acc.w);
        acc.x = fmaf(wv0.w, x0.x, acc.x); acc.y = fmaf(wv1.w, x0.y, acc.y);
        acc.z = fmaf(wv2.w, x0.z, acc.z); acc.w = fmaf(wv3.w, x0.w, acc.w);
        float4 s;
        s.x = __fdividef(acc.x, 1.f + __expf(-acc.x));
        s.y = __fdividef(acc.y, 1.f + __expf(-acc.y));
        s.z = __fdividef(acc.z, 1.f + __expf(-acc.z));
        s.w = __fdividef(acc.w, 1.f + __expf(-acc.w));
        st4h(po + j*DIN, s);
        x3 = x2; x2 = x1; x1 = x0;
    }
}

// ---------------- x_proj (xa fp16) ----------------
__global__ void __launch_bounds__(256)
xproj_k(const float* __restrict__ W) {
    __shared__ __align__(16) float Wsh[XD * DIN];
    for (int i = threadIdx.x; i < XD*DIN; i += 256) Wsh[i] = W[i];
    __syncthreads();
    int warp = threadIdx.x >> 5, lane = threadIdx.x & 31;
    int m0 = blockIdx.x * 32;
    for (int r = warp; r < 32; r += 8) {
        int m = m0 + r;
        const __half* ar = g_xah + (size_t)m * DIN;
        float acc[XD];
        #pragma unroll
        for (int n = 0; n < XD; n++) acc[n] = 0.f;
        #pragma unroll
        for (int it = 0; it < 3; it++) {
            int k4 = lane + it * 32;
            float4 a = ld4h(ar + k4 * 4);
            #pragma unroll
            for (int n = 0; n < XD; n++) {
                const float4 wv = *(const float4*)(Wsh + n*DIN + k4*4);
                acc[n] = fmaf(a.x, wv.x, fmaf(a.y, wv.y, fmaf(a.z, wv.z, fmaf(a.w, wv.w, acc[n]))));
            }
        }
        float myv = 0.f;
        #pragma unroll
        for (int n = 0; n < XD; n++) {
            float v = acc[n];
            #pragma unroll
            for (int off = 16; off > 0; off >>= 1)
                v += __shfl_xor_sync(0xffffffffu, v, off);
            if (lane == n) myv = v;
        }
        if (lane < DTR) g_xdbl[(size_t)m*DTR + lane] = myv;
        else if (lane < XD) g_bc[(size_t)m*8 + lane - DTR] = myv;
    }
}

// ---------------- scan pass 1 ----------------
__global__ void scan1_k(const float* __restrict__ dtw, const float* __restrict__ dtb, int mix) {
    __shared__ float Bsm[LC][4];
    __shared__ float Xd[LC][DTR];
    int chunk = blockIdx.x, b = blockIdx.y, d = threadIdx.x;
    int l0 = chunk * LC;
    if (threadIdx.x < LC*4) {
        int l = threadIdx.x >> 2, s = threadIdx.x & 3;
        Bsm[l][s] = g_bc[((size_t)(b*LLEN + l0 + l))*8 + s];
    }
    {
        int l = threadIdx.x / DTR, r = threadIdx.x - l*DTR;
        Xd[l][r] = g_xdbl[((size_t)(b*LLEN + l0 + l))*DTR + r];
    }
    __syncthreads();
    int slow = g_slow[mix];
    const float* Ab = g_A + (mix*DIN + d)*4;
    float Av0 = Ab[0], Av1 = Ab[1], Av2 = Ab[2], Av3 = Ab[3];
    const float4* w4 = (const float4*)(dtw + d * DTR);
    float4 dw0 = w4[0], dw1 = w4[1], dw2 = w4[2];
    float pb = dtb[d];
    float h0 = 0.f, h1 = 0.f, h2 = 0.f, h3 = 0.f, sd = 0.f;
    const __half* pa = g_xah + (size_t)(b*LLEN + l0)*DIN + d;
    #pragma unroll 4
    for (int l = 0; l < LC; l++) {
        float xav = __half2float(pa[l*DIN]);
        const float* xr = Xd[l];
        float p = pb;
        p = fmaf(xr[0], dw0.x, p);  p = fmaf(xr[1], dw0.y, p);
        p = fmaf(xr[2], dw0.z, p);  p = fmaf(xr[3], dw0.w, p);
        p = fmaf(xr[4], dw1.x, p);  p = fmaf(xr[5], dw1.y, p);
        p = fmaf(xr[6], dw1.z, p);  p = fmaf(xr[7], dw1.w, p);
        p = fmaf(xr[8], dw2.x, p);  p = fmaf(xr[9], dw2.y, p);
        p = fmaf(xr[10], dw2.z, p); p = fmaf(xr[11], dw2.w, p);
        float dtv = (p > 20.f) ? p : __logf(1.f + __expf(p));
        float dbu = dtv * xav;
        sd += dtv;
        float b0 = Bsm[l][0], b1 = Bsm[l][1], b2 = Bsm[l][2], b3 = Bsm[l][3];
        if (!slow) {
            float e = __expf(Av0 * dtv);
            float q = e;
            h0 = fmaf(q, h0, dbu*b0); q *= e;
            h1 = fmaf(q, h1, dbu*b1); q *= e;
            h2 = fmaf(q, h2, dbu*b2); q *= e;
            h3 = fmaf(q, h3, dbu*b3);
        } else {
            h0 = fmaf(__expf(dtv*Av0), h0, dbu*b0);
            h1 = fmaf(__expf(dtv*Av1), h1, dbu*b1);
            h2 = fmaf(__expf(dtv*Av2), h2, dbu*b2);
            h3 = fmaf(__expf(dtv*Av3), h3, dbu*b3);
        }
    }
    int o = ((b*DIN) + d)*NC + chunk;
    ((float4*)g_hpart)[o] = make_float4(h0, h1, h2, h3);
    g_sumdt[o] = sd;
}

// ---------------- scan pass 2 ----------------
__global__ void scan2_k(int mix) {
    int t = blockIdx.x * blockDim.x + threadIdx.x;
    if (t >= BB*DIN) return;
    int d = t % DIN;
    const float* Ab = g_A + (mix*DIN + d)*4;
    float Av0 = Ab[0], Av1 = Ab[1], Av2 = Ab[2], Av3 = Ab[3];
    float H0 = 0.f, H1 = 0.f, H2 = 0.f, H3 = 0.f;
    for (int c = 0; c < NC; c++) {
        int o = t*NC + c;
        ((float4*)g_Hinit)[o] = make_float4(H0, H1, H2, H3);
        float4 hp = ((const float4*)g_hpart)[o];
        float sd = g_sumdt[o];
        H0 = fmaf(__expf(Av0*sd), H0, hp.x);
        H1 = fmaf(__expf(Av1*sd), H1, hp.y);
        H2 = fmaf(__expf(Av2*sd), H2, hp.z);
        H3 = fmaf(__expf(Av3*sd), H3, hp.w);
    }
}

// ---------------- scan pass 3 ----------------
__global__ void scan3_k(const float* __restrict__ dtw, const float* __restrict__ dtb,
                        const float* __restrict__ Dw, int mix, int write_half) {
    __shared__ float Bsm[LC][4];
    __shared__ float Csm[LC][4];
    __shared__ float Xd[LC][DTR];
    int chunk = blockIdx.x, b = blockIdx.y, d = threadIdx.x;
    int l0 = chunk * LC;
    if (threadIdx.x < LC*8) {
        int l = threadIdx.x >> 3, s = threadIdx.x & 7;
        float v = g_bc[((size_t)(b*LLEN + l0 + l))*8 + s];
        if (s < 4) Bsm[l][s] = v; else Csm[l][s-4] = v;
    }
    {
        int l = threadIdx.x / DTR, r = threadIdx.x - l*DTR;
        Xd[l][r] = g_xdbl[((size_t)(b*LLEN + l0 + l))*DTR + r];
    }
    __syncthreads();
    int slow = g_slow[mix];
    const float* Ab = g_A + (mix*DIN + d)*4;
    float Av0 = Ab[0], Av1 = Ab[1], Av2 = Ab[2], Av3 = Ab[3];
    const float4* w4 = (const float4*)(dtw + d * DTR);
    float4 dw0 = w4[0], dw1 = w4[1], dw2 = w4[2];
    float pb = dtb[d];
    float Dd = Dw[d];
    int o = ((b*DIN) + d)*NC + chunk;
    float4 Hi = ((const float4*)g_Hinit)[o];
    float h0 = Hi.x, h1 = Hi.y, h2 = Hi.z, h3 = Hi.w;
    size_t base = (size_t)(b*LLEN + l0)*DIN + d;
    const __half* pa = g_xah + base;
    const __half* pz = g_xzh + (size_t)(b*LLEN + l0)*(2*DIN) + DIN + d;
    #pragma unroll 4
    for (int l = 0; l < LC; l++) {
        float xav = __half2float(pa[l*DIN]);
        const float* xr = Xd[l];
        float p = pb;
        p = fmaf(xr[0], dw0.x, p);  p = fmaf(xr[1], dw0.y, p);
        p = fmaf(xr[2], dw0.z, p);  p = fmaf(xr[3], dw0.w, p);
        p = fmaf(xr[4], dw1.x, p);  p = fmaf(xr[5], dw1.y, p);
        p = fmaf(xr[6], dw1.z, p);  p = fmaf(xr[7], dw1.w, p);
        p = fmaf(xr[8], dw2.x, p);  p = fmaf(xr[9], dw2.y, p);
        p = fmaf(xr[10], dw2.z, p); p = fmaf(xr[11], dw2.w, p);
        float dtv = (p > 20.f) ? p : __logf(1.f + __expf(p));
        float dbu = dtv * xav;
        float b0 = Bsm[l][0], b1 = Bsm[l][1], b2 = Bsm[l][2], b3 = Bsm[l][3];
        if (!slow) {
            float e = __expf(Av0 * dtv);
            float q = e;
            h0 = fmaf(q, h0, dbu*b0); q *= e;
            h1 = fmaf(q, h1, dbu*b1); q *= e;
            h2 = fmaf(q, h2, dbu*b2); q *= e;
            h3 = fmaf(q, h3, dbu*b3);
        } else {
            h0 = fmaf(__expf(dtv*Av0), h0, dbu*b0);
            h1 = fmaf(__expf(dtv*Av1), h1, dbu*b1);
            h2 = fmaf(__expf(dtv*Av2), h2, dbu*b2);
            h3 = fmaf(__expf(dtv*Av3), h3, dbu*b3);
        }
        float y = h0*Csm[l][0] + h1*Csm[l][1] + h2*Csm[l][2] + h3*Csm[l][3];
        y = fmaf(xav, Dd, y);
        float zv = __half2float(pz[l*2*DIN]);
        float zs = __fdividef(zv, 1.f + __expf(-zv));
        float yo = y * zs;
        if (write_half) {
            g_ah[base + l*DIN] = __float2half_rn(yo);
        } else {
            g_y[base + l*DIN] = yo;
        }
    }
}

// ---------------- final ----------------
__global__ void final_k(const float* __restrict__ V,
                        const float* __restrict__ lng, const float* __restrict__ lnb,
                        float* __restrict__ out)
{
    __shared__ __align__(16) float Ufs[4*DIN];
    __shared__ float Vsh[CEMB*4];
    __shared__ float u[32][4];
    __shared__ float vs[32][193];
    __shared__ float mu[32], rsd[32];
    int b = blockIdx.y;
    int l0 = blockIdx.x * 32;
    int tid = threadIdx.x;
    for (int i = tid; i < 4*DIN; i += 256) Ufs[i] = g_Uf[i];
    for (int i = tid; i < 4*CEMB; i += 256) Vsh[i] = V[i];
    __syncthreads();
    if (tid < 128) {
        int p = tid >> 2, r = tid & 3;
        const float4* yr = (const float4*)(g_y + ((size_t)(b*LLEN) + l0 + p)*DIN);
        const float4* uf = (const float4*)(Ufs + r*DIN);
        float a = 0.f;
        #pragma unroll 8
        for (int c = 0; c < DIN/4; c++) {
            float4 yv = yr[c];
            float4 wv = uf[c];
            a = fmaf(yv.x, wv.x, fmaf(yv.y, wv.y, fmaf(yv.z, wv.z, fmaf(yv.w, wv.w, a))));
        }
        u[p][r] = a;
    }
    __syncthreads();
    for (int i = tid; i < 32*CEMB; i += 256) {
        int p = i / CEMB, c = i % CEMB;
        float v = g_xh[((size_t)(b*LLEN) + l0 + p)*CEMB + c];
        v = fmaf(Vsh[c*4+0], u[p][0], v);
        v = fmaf(Vsh[c*4+1], u[p][1], v);
        v = fmaf(Vsh[c*4+2], u[p][2], v);
        v = fmaf(Vsh[c*4+3], u[p][3], v);
        vs[p][c] = v;
    }
    __syncthreads();
    int warp = tid >> 5, lane = tid & 31;
    #pragma unroll
    for (int pp = 0; pp < 4; pp++) {
        int p = warp*4 + pp;
        float s = 0.f, ss = 0.f;
        for (int c = lane; c < CEMB; c += 32) {
            float v = vs[p][c];
            s += v; ss = fmaf(v, v, ss);
        }
        #pragma unroll
        for (int off = 16; off > 0; off >>= 1) {
            s  += __shfl_xor_sync(0xffffffffu, s, off);
            ss += __shfl_xor_sync(0xffffffffu, ss, off);
        }
        if (lane == 0) {
            float m = s * (1.f/CEMB);
            mu[p] = m;
            rsd[p] = rsqrtf(ss * (1.f/CEMB) - m*m + 1e-5f);
        }
    }
    __syncthreads();
    for (int c = warp; c < CEMB; c += 8) {
        int p = lane;
        float v = (vs[p][c] - mu[p]) * rsd[p] * lng[c] + lnb[c];
        out[((size_t)(b*CEMB) + c)*LLEN + l0 + lane] = v;
    }
}

// ---------------- launch ----------------
extern "C" void kernel_launch(void* const* d_in, const int* in_sizes, int n_in,
                              void* d_out, int out_size)
{
    const float* x         = (const float*)d_in[0];
    const float* in_proj_w = (const float*)d_in[1];
    const float* conv_w    = (const float*)d_in[2];
    const float* conv_b    = (const float*)d_in[3];
    const float* x_proj_w  = (const float*)d_in[4];
    const float* dt_proj_w = (const float*)d_in[5];
    const float* dt_proj_b = (const float*)d_in[6];
    const float* A_log     = (const float*)d_in[7];
    const float* Dw        = (const float*)d_in[8];
    const float* out_proj_w= (const float*)d_in[9];
    const float* U_w       = (const float*)d_in[10];
    const float* V_w       = (const float*)d_in[11];
    const float* ln_g      = (const float*)d_in[12];
    const float* ln_b      = (const float*)d_in[13];
    float* out = (float*)d_out;

    __half *xzh_p, *ah_p, *bh_p, *wh_p;
    cudaGetSymbolAddress((void**)&xzh_p, g_xzh);
    cudaGetSymbolAddress((void**)&ah_p, g_ah);
    cudaGetSymbolAddress((void**)&bh_p, g_bh);
    cudaGetSymbolAddress((void**)&wh_p, g_wh);

    const int IPW4 = 2*DIN*CEMB/4;      // 36864 float4 per in_proj mix
    const int OPW4 = CEMB*DIN/4;        // 18432

    // weight conversions (independent of data path; launched upfront)
    wcvt_k<<<(IPW4 + 255)/256, 256>>>(in_proj_w, IPW4, 0);
    wcvt_k<<<(IPW4 + 255)/256, 256>>>(in_proj_w + (size_t)2*DIN*CEMB, IPW4, IPW4);
    wcvt_k<<<(OPW4 + 255)/256, 256>>>(out_proj_w, OPW4, 2*IPW4);
    transpose_k<<<dim3(LLEN/32, CEMB/32, BB), dim3(32, 8)>>>(x);
    prepA_k<<<2, DIN>>>(A_log);
    uf_k<<<1, DIN>>>(U_w, out_proj_w + (size_t)CEMB*DIN);

    for (int mix = 0; mix < 2; mix++) {
        const float* dtw = dt_proj_w + (size_t)mix*DIN*DTR;
        const float* dtb = dt_proj_b + mix*DIN;
        const __half* Ain = (mix == 0) ? ah_p : bh_p;

        gemm_mma<<<dim3((2*DIN)/64, MROWS/128), 256>>>(
            Ain, wh_p + (size_t)mix*IPW4*4, nullptr, xzh_p, MROWS, 2*DIN, CEMB, 1);
        conv_k<<<((MROWS/8)*(DIN/4) + 255)/256, 256>>>(conv_w + mix*DIN*4, conv_b + mix*DIN);
        xproj_k<<<MROWS/32, 256>>>(x_proj_w + (size_t)mix*XD*DIN);
        scan1_k<<<dim3(NC, BB), DIN>>>(dtw, dtb, mix);
        scan2_k<<<(BB*DIN + 255)/256, 256>>>(mix);
        scan3_k<<<dim3(NC, BB), DIN>>>(dtw, dtb, Dw + mix*DIN, mix, mix == 0 ? 1 : 0);
        if (mix == 0) {
            gemm_mma<<<dim3(CEMB/64, MROWS/128), 256>>>(
                ah_p, wh_p + (size_t)2*IPW4*4, nullptr, bh_p, MROWS, CEMB, DIN, 1);
        }
    }

    final_k<<<dim3(LLEN/32, BB), 256>>>(V_w, ln_g, ln_b, out);
}

// round 16
// speedup vs baseline: 1.5207x; 1.2034x over previous
#include <cuda_runtime.h>
#include <cuda_fp16.h>
#include <cstdint>

#define BB   8
#define LLEN 4096
#define CEMB 192
#define DIN  384
#define XD   20
#define DTR  12
#define NC   128
#define LC   32
#define MROWS (BB*LLEN)

// ---------------- scratch ----------------
__device__ float g_xh  [MROWS*CEMB];
__device__ __half g_xzh[MROWS*2*DIN];     // in_proj output (fp16)
__device__ __half g_xah[MROWS*DIN];       // conv+silu output (fp16)
__device__ float g_xd64[MROWS*64];        // x_dbl padded to 64 (dt_lr 0..11 | B 12..15 | C 16..19)
__device__ float g_y   [MROWS*DIN];
__device__ float g_hpart[BB*DIN*NC*4];
__device__ float g_sumdt[BB*DIN*NC];
__device__ float g_Hinit[BB*DIN*NC*4];
__device__ float g_A[2*DIN*4];
__device__ int   g_slow[2];
__device__ float g_Uf[4*DIN];
__device__ __half g_ah[MROWS*DIN];        // xh then y (GEMM A operand)
__device__ __half g_bh[MROWS*CEMB];       // h2
__device__ __half g_wh[2*768*CEMB + CEMB*DIN];  // inproj0 | inproj1 | outproj0
__device__ __half g_wxp[2*64*DIN];        // padded x_proj weights

__device__ __forceinline__ uint32_t smem_u32(const void* p) {
    uint32_t a;
    asm("{ .reg .u64 t; cvta.to.shared.u64 t, %1; cvt.u32.u64 %0, t; }" : "=r"(a) : "l"(p));
    return a;
}
__device__ __forceinline__ float4 ld4h(const __half* p) {
    uint2 u = *(const uint2*)p;
    __half2 h0 = *(__half2*)&u.x, h1 = *(__half2*)&u.y;
    float2 f0 = __half22float2(h0), f1 = __half22float2(h1);
    return make_float4(f0.x, f0.y, f1.x, f1.y);
}
__device__ __forceinline__ void st4h(__half* p, float4 v) {
    uint32_t p0, p1;
    asm("cvt.rn.f16x2.f32 %0, %1, %2;" : "=r"(p0) : "f"(v.y), "f"(v.x));
    asm("cvt.rn.f16x2.f32 %0, %1, %2;" : "=r"(p1) : "f"(v.w), "f"(v.z));
    *(uint2*)p = make_uint2(p0, p1);
}

#define LDSM_X4(r0, r1, r2, r3, addr) \
    asm volatile("ldmatrix.sync.aligned.m8n8.x4.shared.b16 {%0,%1,%2,%3}, [%4];" \
        : "=r"(r0), "=r"(r1), "=r"(r2), "=r"(r3) : "r"(addr))
#define LDSM_X2(r0, r1, addr) \
    asm volatile("ldmatrix.sync.aligned.m8n8.x2.shared.b16 {%0,%1}, [%2];" \
        : "=r"(r0), "=r"(r1) : "r"(addr))
#define MMA_F16(c, a, b) \
    asm volatile("mma.sync.aligned.m16n8k16.row.col.f32.f16.f16.f32 " \
        "{%0,%1,%2,%3}, {%4,%5,%6,%7}, {%8,%9}, {%0,%1,%2,%3};" \
        : "+f"((c)[0]), "+f"((c)[1]), "+f"((c)[2]), "+f"((c)[3]) \
        : "r"((a)[0]), "r"((a)[1]), "r"((a)[2]), "r"((a)[3]), "r"((b)[0]), "r"((b)[1]))

// ======================= fp16 HMMA GEMM, register-prefetch pipelined =======================
__global__ void __launch_bounds__(256, 2)
gemm_mma(const __half* __restrict__ A, const __half* __restrict__ W,
         float* __restrict__ C, __half* __restrict__ Ch,
         int M, int N, int K, int out_half)
{
    __shared__ __align__(1024) char sm[24576];
    char* AH = sm;
    char* WH = sm + 16384;

    const int tid = threadIdx.x, wid = tid >> 5, lane = tid & 31;
    const int wm = wid & 3, wn = wid >> 2;
    const int bm = blockIdx.y * 128, bn = blockIdx.x * 64;
    const uint32_t sAH = smem_u32(AH), sWH = smem_u32(WH);

    float acc[2][4][4];
    #pragma unroll
    for (int i = 0; i < 2; i++)
        #pragma unroll
        for (int j = 0; j < 4; j++)
            #pragma unroll
            for (int q = 0; q < 4; q++) acc[i][j][q] = 0.f;

    uint4 ra[4], rw[2];
    const int nkt = K >> 6;

    #pragma unroll
    for (int i = 0; i < 4; i++) {
        int idx = tid + i * 256, r = idx >> 3, q = idx & 7;
        ra[i] = *(const uint4*)(A + (size_t)(bm + r) * K + q * 8);
    }
    #pragma unroll
    for (int i = 0; i < 2; i++) {
        int idx = tid + i * 256, r = idx >> 3, q = idx & 7;
        rw[i] = *(const uint4*)(W + (size_t)(bn + r) * K + q * 8);
    }

    for (int kt = 0; kt < nkt; kt++) {
        #pragma unroll
        for (int i = 0; i < 4; i++) {
            int idx = tid + i * 256, r = idx >> 3, q = idx & 7;
            *(uint4*)(AH + r * 128 + ((q ^ (r & 7)) << 4)) = ra[i];
        }
        #pragma unroll
        for (int i = 0; i < 2; i++) {
            int idx = tid + i * 256, r = idx >> 3, q = idx & 7;
            *(uint4*)(WH + r * 128 + ((q ^ (r & 7)) << 4)) = rw[i];
        }
        __syncthreads();

        if (kt + 1 < nkt) {
            int k0 = (kt + 1) * 64;
            #pragma unroll
            for (int i = 0; i < 4; i++) {
                int idx = tid + i * 256, r = idx >> 3, q = idx & 7;
                ra[i] = *(const uint4*)(A + (size_t)(bm + r) * K + k0 + q * 8);
            }
            #pragma unroll
            for (int i = 0; i < 2; i++) {
                int idx = tid + i * 256, r = idx >> 3, q = idx & 7;
                rw[i] = *(const uint4*)(W + (size_t)(bn + r) * K + k0 + q * 8);
            }
        }

        #pragma unroll
        for (int ks = 0; ks < 4; ks++) {
            uint32_t ah[2][4], bh[4][2];
            #pragma unroll
            for (int mt = 0; mt < 2; mt++) {
                int r = wm * 32 + mt * 16 + (lane & 15);
                int c16 = ks * 2 + (lane >> 4);
                LDSM_X4(ah[mt][0], ah[mt][1], ah[mt][2], ah[mt][3],
                        sAH + r * 128 + ((c16 ^ (r & 7)) << 4));
            }
            #pragma unroll
            for (int nt = 0; nt < 4; nt++) {
                int rn = wn * 32 + nt * 8 + (lane & 7);
                int c16 = ks * 2 + ((lane >> 3) & 1);
                LDSM_X2(bh[nt][0], bh[nt][1],
                        sWH + rn * 128 + ((c16 ^ (rn & 7)) << 4));
            }
            #pragma unroll
            for (int mt = 0; mt < 2; mt++)
                #pragma unroll
                for (int nt = 0; nt < 4; nt++)
                    MMA_F16(acc[mt][nt], ah[mt], bh[nt]);
        }
        __syncthreads();
    }

    if (!out_half) {
        #pragma unroll
        for (int mt = 0; mt < 2; mt++) {
            int row = bm + wm * 32 + mt * 16 + (lane >> 2);
            #pragma unroll
            for (int nt = 0; nt < 4; nt++) {
                int col = bn + wn * 32 + nt * 8 + (lane & 3) * 2;
                *(float2*)(C + (size_t)row * N + col)       = make_float2(acc[mt][nt][0], acc[mt][nt][1]);
                *(float2*)(C + (size_t)(row + 8) * N + col) = make_float2(acc[mt][nt][2], acc[mt][nt][3]);
            }
        }
    } else {
        #pragma unroll
        for (int mt = 0; mt < 2; mt++) {
            int row = bm + wm * 32 + mt * 16 + (lane >> 2);
            #pragma unroll
            for (int nt = 0; nt < 4; nt++) {
                int col = bn + wn * 32 + nt * 8 + (lane & 3) * 2;
                #pragma unroll
                for (int hh = 0; hh < 2; hh++) {
                    uint32_t hp;
                    asm("cvt.rn.f16x2.f32 %0, %1, %2;" : "=r"(hp)
                        : "f"(acc[mt][nt][hh*2+1]), "f"(acc[mt][nt][hh*2+0]));
                    *(uint32_t*)(Ch + (size_t)(row + hh*8) * N + col) = hp;
                }
            }
        }
    }
}

// ---------------- weight convert: fp32 -> fp16 at offset ----------------
__global__ void wcvt_k(const float* __restrict__ src, int n4, int dst4) {
    int idx = blockIdx.x * blockDim.x + threadIdx.x;
    if (idx >= n4) return;
    float4 v = ((const float4*)src)[idx];
    uint32_t p0, p1;
    asm("cvt.rn.f16x2.f32 %0, %1, %2;" : "=r"(p0) : "f"(v.y), "f"(v.x));
    asm("cvt.rn.f16x2.f32 %0, %1, %2;" : "=r"(p1) : "f"(v.w), "f"(v.z));
    ((uint2*)g_wh)[dst4 + idx] = make_uint2(p0, p1);
}

// ---------------- x_proj weight: [20,384] fp32 -> [64,384] fp16 padded ----------------
__global__ void wcvtx_k(const float* __restrict__ src, int mix) {
    int idx = blockIdx.x * blockDim.x + threadIdx.x;   // over 64*DIN/4 = 6144
    if (idx >= 64 * DIN / 4) return;
    int n = (idx * 4) / DIN;
    uint2 o = make_uint2(0, 0);
    if (n < XD) {
        float4 v = ((const float4*)src)[idx];
        asm("cvt.rn.f16x2.f32 %0, %1, %2;" : "=r"(o.x) : "f"(v.y), "f"(v.x));
        asm("cvt.rn.f16x2.f32 %0, %1, %2;" : "=r"(o.y) : "f"(v.w), "f"(v.z));
    }
    ((uint2*)(g_wxp + (size_t)mix * 64 * DIN))[idx] = o;
}

// ---------------- transpose (B,C,L) -> (B,L,C), fp32 + fp16 ----------------
__global__ void transpose_k(const float* __restrict__ x) {
    __shared__ float t[32][33];
    int b = blockIdx.z;
    int l0 = blockIdx.x * 32, c0 = blockIdx.y * 32;
    int tx = threadIdx.x, ty = threadIdx.y;
    #pragma unroll
    for (int j = ty; j < 32; j += 8)
        t[j][tx] = x[((b*CEMB) + (c0 + j)) * LLEN + l0 + tx];
    __syncthreads();
    #pragma unroll
    for (int j = ty; j < 32; j += 8) {
        float v = t[tx][j];
        size_t idx = ((size_t)(b*LLEN) + (l0 + j)) * CEMB + c0 + tx;
        g_xh[idx] = v;
        g_ah[idx] = __float2half_rn(v);
    }
}

// ---------------- A structure prep ----------------
__global__ void prepA_k(const float* __restrict__ A_log) {
    int mix = blockIdx.x;
    int d = threadIdx.x;
    if (d == 0) g_slow[mix] = 0;
    __syncthreads();
    const float* al = A_log + mix * DIN * 4;
    float a[4];
    #pragma unroll
    for (int s = 0; s < 4; s++) {
        a[s] = -expf(al[d*4 + s]);
        g_A[(mix*DIN + d)*4 + s] = a[s];
    }
    bool ok = true;
    #pragma unroll
    for (int s = 0; s < 4; s++) {
        float want = (float)(s + 1) * a[0];
        if (fabsf(a[s] - want) > 1e-5f * fabsf(a[s]) + 1e-7f) ok = false;
    }
    if (!ok) atomicExch(&g_slow[mix], 1);
}

// ---------------- Uf = U_w @ Wout2 ----------------
__global__ void uf_k(const float* __restrict__ U, const float* __restrict__ Wout2) {
    __shared__ float Ush[4*CEMB];
    int k = threadIdx.x;
    for (int i = k; i < 4*CEMB; i += DIN) Ush[i] = U[i];
    __syncthreads();
    float acc0 = 0.f, acc1 = 0.f, acc2 = 0.f, acc3 = 0.f;
    for (int c = 0; c < CEMB; c++) {
        float w = Wout2[(size_t)c * DIN + k];
        acc0 = fmaf(Ush[0*CEMB + c], w, acc0);
        acc1 = fmaf(Ush[1*CEMB + c], w, acc1);
        acc2 = fmaf(Ush[2*CEMB + c], w, acc2);
        acc3 = fmaf(Ush[3*CEMB + c], w, acc3);
    }
    g_Uf[0*DIN + k] = acc0;
    g_Uf[1*DIN + k] = acc1;
    g_Uf[2*DIN + k] = acc2;
    g_Uf[3*DIN + k] = acc3;
}

// ---------------- depthwise causal conv + silu, rolling window, fp16 IO ----------------
__global__ void __launch_bounds__(256)
conv_k(const float* __restrict__ w, const float* __restrict__ bias) {
    int idx = blockIdx.x * blockDim.x + threadIdx.x;
    if (idx >= (MROWS/8) * (DIN/4)) return;
    int d4 = idx % (DIN/4);
    int m8 = idx / (DIN/4);
    int d  = d4 * 4;
    int bl = m8 * 8;
    int l  = bl % LLEN;

    float4 wv0 = *(const float4*)(w + (d+0)*4);
    float4 wv1 = *(const float4*)(w + (d+1)*4);
    float4 wv2 = *(const float4*)(w + (d+2)*4);
    float4 wv3 = *(const float4*)(w + (d+3)*4);
    float4 bv  = *(const float4*)(bias + d);

    const __half* p = g_xzh + (size_t)bl * (2*DIN) + d;
    __half* po = g_xah + (size_t)bl * DIN + d;
    float4 x1 = make_float4(0,0,0,0), x2 = x1, x3 = x1;
    if (l) {
        x3 = ld4h(p - 3*2*DIN);
        x2 = ld4h(p - 2*2*DIN);
        x1 = ld4h(p - 2*DIN);
    }
    #pragma unroll
    for (int j = 0; j < 8; j++) {
        float4 x0 = ld4h(p + j*2*DIN);
        float4 acc = bv;
        acc.x = fmaf(wv0.x, x3.x, acc.x); acc.y = fmaf(wv1.x, x3.y, acc.y);
        acc.z = fmaf(wv2.x, x3.z, acc.z); acc.w = fmaf(wv3.x, x3.w, acc.w);
        acc.x = fmaf(wv0.y, x2.x, acc.x); acc.y = fmaf(wv1.y, x2.y, acc.y);
        acc.z = fmaf(wv2.y, x2.z, acc.z); acc.w = fmaf(wv3.y, x2.w, acc.w);
        acc.x = fmaf(wv0.z, x1.x, acc.x); acc.y = fmaf(wv1.z, x1.y, acc.y);
        acc.z = fmaf(wv2.z, x1.z, acc.z); acc.w = fmaf(wv3.z, x1.w, acc.w);
        acc.x = fmaf(wv0.w, x0.x, acc.x); acc.y = fmaf(wv1.w, x0.y, acc.y);
        acc.z = fmaf(wv2.w, x0.z, acc.z); acc.w = fmaf(wv3.w, x0.w, acc.w);
        float4 s;
        s.x = __fdividef(acc.x, 1.f + __expf(-acc.x));
        s.y = __fdividef(acc.y, 1.f + __expf(-acc.y));
        s.z = __fdividef(acc.z, 1.f + __expf(-acc.z));
        s.w = __fdividef(acc.w, 1.f + __expf(-acc.w));
        st4h(po + j*DIN, s);
        x3 = x2; x2 = x1; x1 = x0;
    }
}

// ---------------- scan pass 1 ----------------
__global__ void scan1_k(const float* __restrict__ dtw, const float* __restrict__ dtb, int mix) {
    __shared__ float Bsm[LC][4];
    __shared__ float Xd[LC][DTR];
    int chunk = blockIdx.x, b = blockIdx.y, d = threadIdx.x;
    int l0 = chunk * LC;
    if (threadIdx.x < LC*4) {
        int l = threadIdx.x >> 2, s = threadIdx.x & 3;
        Bsm[l][s] = g_xd64[((size_t)(b*LLEN + l0 + l))*64 + DTR + s];
    }
    {
        int l = threadIdx.x / DTR, r = threadIdx.x - l*DTR;
        Xd[l][r] = g_xd64[((size_t)(b*LLEN + l0 + l))*64 + r];
    }
    __syncthreads();
    int slow = g_slow[mix];
    const float* Ab = g_A + (mix*DIN + d)*4;
    float Av0 = Ab[0], Av1 = Ab[1], Av2 = Ab[2], Av3 = Ab[3];
    const float4* w4 = (const float4*)(dtw + d * DTR);
    float4 dw0 = w4[0], dw1 = w4[1], dw2 = w4[2];
    float pb = dtb[d];
    float h0 = 0.f, h1 = 0.f, h2 = 0.f, h3 = 0.f, sd = 0.f;
    const __half* pa = g_xah + (size_t)(b*LLEN + l0)*DIN + d;
    #pragma unroll 4
    for (int l = 0; l < LC; l++) {
        float xav = __half2float(pa[l*DIN]);
        const float* xr = Xd[l];
        float p = pb;
        p = fmaf(xr[0], dw0.x, p);  p = fmaf(xr[1], dw0.y, p);
        p = fmaf(xr[2], dw0.z, p);  p = fmaf(xr[3], dw0.w, p);
        p = fmaf(xr[4], dw1.x, p);  p = fmaf(xr[5], dw1.y, p);
        p = fmaf(xr[6], dw1.z, p);  p = fmaf(xr[7], dw1.w, p);
        p = fmaf(xr[8], dw2.x, p);  p = fmaf(xr[9], dw2.y, p);
        p = fmaf(xr[10], dw2.z, p); p = fmaf(xr[11], dw2.w, p);
        float dtv = (p > 20.f) ? p : __logf(1.f + __expf(p));
        float dbu = dtv * xav;
        sd += dtv;
        float b0 = Bsm[l][0], b1 = Bsm[l][1], b2 = Bsm[l][2], b3 = Bsm[l][3];
        if (!slow) {
            float e = __expf(Av0 * dtv);
            float q = e;
            h0 = fmaf(q, h0, dbu*b0); q *= e;
            h1 = fmaf(q, h1, dbu*b1); q *= e;
            h2 = fmaf(q, h2, dbu*b2); q *= e;
            h3 = fmaf(q, h3, dbu*b3);
        } else {
            h0 = fmaf(__expf(dtv*Av0), h0, dbu*b0);
            h1 = fmaf(__expf(dtv*Av1), h1, dbu*b1);
            h2 = fmaf(__expf(dtv*Av2), h2, dbu*b2);
            h3 = fmaf(__expf(dtv*Av3), h3, dbu*b3);
        }
    }
    int o = ((b*DIN) + d)*NC + chunk;
    ((float4*)g_hpart)[o] = make_float4(h0, h1, h2, h3);
    g_sumdt[o] = sd;
}

// ---------------- scan pass 2 ----------------
__global__ void scan2_k(int mix) {
    int t = blockIdx.x * blockDim.x + threadIdx.x;
    if (t >= BB*DIN) return;
    int d = t % DIN;
    const float* Ab = g_A + (mix*DIN + d)*4;
    float Av0 = Ab[0], Av1 = Ab[1], Av2 = Ab[2], Av3 = Ab[3];
    float H0 = 0.f, H1 = 0.f, H2 = 0.f, H3 = 0.f;
    for (int c = 0; c < NC; c++) {
        int o = t*NC + c;
        ((float4*)g_Hinit)[o] = make_float4(H0, H1, H2, H3);
        float4 hp = ((const float4*)g_hpart)[o];
        float sd = g_sumdt[o];
        H0 = fmaf(__expf(Av0*sd), H0, hp.x);
        H1 = fmaf(__expf(Av1*sd), H1, hp.y);
        H2 = fmaf(__expf(Av2*sd), H2, hp.z);
        H3 = fmaf(__expf(Av3*sd), H3, hp.w);
    }
}

// ---------------- scan pass 3 ----------------
__global__ void scan3_k(const float* __restrict__ dtw, const float* __restrict__ dtb,
                        const float* __restrict__ Dw, int mix, int write_half) {
    __shared__ float Bsm[LC][4];
    __shared__ float Csm[LC][4];
    __shared__ float Xd[LC][DTR];
    int chunk = blockIdx.x, b = blockIdx.y, d = threadIdx.x;
    int l0 = chunk * LC;
    if (threadIdx.x < LC*8) {
        int l = threadIdx.x >> 3, s = threadIdx.x & 7;
        float v = g_xd64[((size_t)(b*LLEN + l0 + l))*64 + DTR + s];
        if (s < 4) Bsm[l][s] = v; else Csm[l][s-4] = v;
    }
    {
        int l = threadIdx.x / DTR, r = threadIdx.x - l*DTR;
        Xd[l][r] = g_xd64[((size_t)(b*LLEN + l0 + l))*64 + r];
    }
    __syncthreads();
    int slow = g_slow[mix];
    const float* Ab = g_A + (mix*DIN + d)*4;
    float Av0 = Ab[0], Av1 = Ab[1], Av2 = Ab[2], Av3 = Ab[3];
    const float4* w4 = (const float4*)(dtw + d * DTR);
    float4 dw0 = w4[0], dw1 = w4[1], dw2 = w4[2];
    float pb = dtb[d];
    float Dd = Dw[d];
    int o = ((b*DIN) + d)*NC + chunk;
    float4 Hi = ((const float4*)g_Hinit)[o];
    float h0 = Hi.x, h1 = Hi.y, h2 = Hi.z, h3 = Hi.w;
    size_t base = (size_t)(b*LLEN + l0)*DIN + d;
    const __half* pa = g_xah + base;
    const __half* pz = g_xzh + (size_t)(b*LLEN + l0)*(2*DIN) + DIN + d;
    #pragma unroll 4
    for (int l = 0; l < LC; l++) {
        float xav = __half2float(pa[l*DIN]);
        const float* xr = Xd[l];
        float p = pb;
        p = fmaf(xr[0], dw0.x, p);  p = fmaf(xr[1], dw0.y, p);
        p = fmaf(xr[2], dw0.z, p);  p = fmaf(xr[3], dw0.w, p);
        p = fmaf(xr[4], dw1.x, p);  p = fmaf(xr[5], dw1.y, p);
        p = fmaf(xr[6], dw1.z, p);  p = fmaf(xr[7], dw1.w, p);
        p = fmaf(xr[8], dw2.x, p);  p = fmaf(xr[9], dw2.y, p);
        p = fmaf(xr[10], dw2.z, p); p = fmaf(xr[11], dw2.w, p);
        float dtv = (p > 20.f) ? p : __logf(1.f + __expf(p));
        float dbu = dtv * xav;
        float b0 = Bsm[l][0], b1 = Bsm[l][1], b2 = Bsm[l][2], b3 = Bsm[l][3];
        if (!slow) {
            float e = __expf(Av0 * dtv);
            float q = e;
            h0 = fmaf(q, h0, dbu*b0); q *= e;
            h1 = fmaf(q, h1, dbu*b1); q *= e;
            h2 = fmaf(q, h2, dbu*b2); q *= e;
            h3 = fmaf(q, h3, dbu*b3);
        } else {
            h0 = fmaf(__expf(dtv*Av0), h0, dbu*b0);
            h1 = fmaf(__expf(dtv*Av1), h1, dbu*b1);
            h2 = fmaf(__expf(dtv*Av2), h2, dbu*b2);
            h3 = fmaf(__expf(dtv*Av3), h3, dbu*b3);
        }
        float y = h0*Csm[l][0] + h1*Csm[l][1] + h2*Csm[l][2] + h3*Csm[l][3];
        y = fmaf(xav, Dd, y);
        float zv = __half2float(pz[l*2*DIN]);
        float zs = __fdividef(zv, 1.f + __expf(-zv));
        float yo = y * zs;
        if (write_half) {
            g_ah[base + l*DIN] = __float2half_rn(yo);
        } else {
            g_y[base + l*DIN] = yo;
        }
    }
}

// ---------------- final ----------------
__global__ void final_k(const float* __restrict__ V,
                        const float* __restrict__ lng, const float* __restrict__ lnb,
                        float* __restrict__ out)
{
    __shared__ __align__(16) float Ufs[4*DIN];
    __shared__ float Vsh[CEMB*4];
    __shared__ float u[32][4];
    __shared__ float vs[32][193];
    __shared__ float mu[32], rsd[32];
    int b = blockIdx.y;
    int l0 = blockIdx.x * 32;
    int tid = threadIdx.x;
    for (int i = tid; i < 4*DIN; i += 256) Ufs[i] = g_Uf[i];
    for (int i = tid; i < 4*CEMB; i += 256) Vsh[i] = V[i];
    __syncthreads();
    if (tid < 128) {
        int p = tid >> 2, r = tid & 3;
        const float4* yr = (const float4*)(g_y + ((size_t)(b*LLEN) + l0 + p)*DIN);
        const float4* uf = (const float4*)(Ufs + r*DIN);
        float a = 0.f;
        #pragma unroll 8
        for (int c = 0; c < DIN/4; c++) {
            float4 yv = yr[c];
            float4 wv = uf[c];
            a = fmaf(yv.x, wv.x, fmaf(yv.y, wv.y, fmaf(yv.z, wv.z, fmaf(yv.w, wv.w, a))));
        }
        u[p][r] = a;
    }
    __syncthreads();
    for (int i = tid; i < 32*CEMB; i += 256) {
        int p = i / CEMB, c = i % CEMB;
        float v = g_xh[((size_t)(b*LLEN) + l0 + p)*CEMB + c];
        v = fmaf(Vsh[c*4+0], u[p][0], v);
        v = fmaf(Vsh[c*4+1], u[p][1], v);
        v = fmaf(Vsh[c*4+2], u[p][2], v);
        v = fmaf(Vsh[c*4+3], u[p][3], v);
        vs[p][c] = v;
    }
    __syncthreads();
    int warp = tid >> 5, lane = tid & 31;
    #pragma unroll
    for (int pp = 0; pp < 4; pp++) {
        int p = warp*4 + pp;
        float s = 0.f, ss = 0.f;
        for (int c = lane; c < CEMB; c += 32) {
            float v = vs[p][c];
            s += v; ss = fmaf(v, v, ss);
        }
        #pragma unroll
        for (int off = 16; off > 0; off >>= 1) {
            s  += __shfl_xor_sync(0xffffffffu, s, off);
            ss += __shfl_xor_sync(0xffffffffu, ss, off);
        }
        if (lane == 0) {
            float m = s * (1.f/CEMB);
            mu[p] = m;
            rsd[p] = rsqrtf(ss * (1.f/CEMB) - m*m + 1e-5f);
        }
    }
    __syncthreads();
    for (int c = warp; c < CEMB; c += 8) {
        int p = lane;
        float v = (vs[p][c] - mu[p]) * rsd[p] * lng[c] + lnb[c];
        out[((size_t)(b*CEMB) + c)*LLEN + l0 + lane] = v;
    }
}

// ---------------- launch ----------------
extern "C" void kernel_launch(void* const* d_in, const int* in_sizes, int n_in,
                              void* d_out, int out_size)
{
    const float* x         = (const float*)d_in[0];
    const float* in_proj_w = (const float*)d_in[1];
    const float* conv_w    = (const float*)d_in[2];
    const float* conv_b    = (const float*)d_in[3];
    const float* x_proj_w  = (const float*)d_in[4];
    const float* dt_proj_w = (const float*)d_in[5];
    const float* dt_proj_b = (const float*)d_in[6];
    const float* A_log     = (const float*)d_in[7];
    const float* Dw        = (const float*)d_in[8];
    const float* out_proj_w= (const float*)d_in[9];
    const float* U_w       = (const float*)d_in[10];
    const float* V_w       = (const float*)d_in[11];
    const float* ln_g      = (const float*)d_in[12];
    const float* ln_b      = (const float*)d_in[13];
    float* out = (float*)d_out;

    __half *xzh_p, *xah_p, *ah_p, *bh_p, *wh_p, *wxp_p;
    float *xd64_p;
    cudaGetSymbolAddress((void**)&xzh_p, g_xzh);
    cudaGetSymbolAddress((void**)&xah_p, g_xah);
    cudaGetSymbolAddress((void**)&ah_p, g_ah);
    cudaGetSymbolAddress((void**)&bh_p, g_bh);
    cudaGetSymbolAddress((void**)&wh_p, g_wh);
    cudaGetSymbolAddress((void**)&wxp_p, g_wxp);
    cudaGetSymbolAddress((void**)&xd64_p, g_xd64);

    const int IPW4 = 2*DIN*CEMB/4;
    const int OPW4 = CEMB*DIN/4;

    wcvt_k<<<(IPW4 + 255)/256, 256>>>(in_proj_w, IPW4, 0);
    wcvt_k<<<(IPW4 + 255)/256, 256>>>(in_proj_w + (size_t)2*DIN*CEMB, IPW4, IPW4);
    wcvt_k<<<(OPW4 + 255)/256, 256>>>(out_proj_w, OPW4, 2*IPW4);
    wcvtx_k<<<(64*DIN/4 + 255)/256, 256>>>(x_proj_w, 0);
    wcvtx_k<<<(64*DIN/4 + 255)/256, 256>>>(x_proj_w + (size_t)XD*DIN, 1);
    transpose_k<<<dim3(LLEN/32, CEMB/32, BB), dim3(32, 8)>>>(x);
    prepA_k<<<2, DIN>>>(A_log);
    uf_k<<<1, DIN>>>(U_w, out_proj_w + (size_t)CEMB*DIN);

    for (int mix = 0; mix < 2; mix++) {
        const float* dtw = dt_proj_w + (size_t)mix*DIN*DTR;
        const float* dtb = dt_proj_b + mix*DIN;
        const __half* Ain = (mix == 0) ? ah_p : bh_p;

        gemm_mma<<<dim3((2*DIN)/64, MROWS/128), 256>>>(
            Ain, wh_p + (size_t)mix*IPW4*4, nullptr, xzh_p, MROWS, 2*DIN, CEMB, 1);
        conv_k<<<((MROWS/8)*(DIN/4) + 255)/256, 256>>>(conv_w + mix*DIN*4, conv_b + mix*DIN);
        gemm_mma<<<dim3(1, MROWS/128), 256>>>(
            xah_p, wxp_p + (size_t)mix*64*DIN, xd64_p, nullptr, MROWS, 64, DIN, 0);
        scan1_k<<<dim3(NC, BB), DIN>>>(dtw, dtb, mix);
        scan2_k<<<(BB*DIN + 255)/256, 256>>>(mix);
        scan3_k<<<dim3(NC, BB), DIN>>>(dtw, dtb, Dw + mix*DIN, mix, mix == 0 ? 1 : 0);
        if (mix == 0) {
            gemm_mma<<<dim3(CEMB/64, MROWS/128), 256>>>(
                ah_p, wh_p + (size_t)2*IPW4*4, nullptr, bh_p, MROWS, CEMB, DIN, 1);
        }
    }

    final_k<<<dim3(LLEN/32, BB), 256>>>(V_w, ln_g, ln_b, out);
}